// round 7
// baseline (speedup 1.0000x reference)
#include <cuda_runtime.h>
#include <cuda_fp16.h>
#include <cstdint>
#include <math.h>

// Problem constants
#define BB 4
#define TT 4096
#define DD 1024
#define HH 16
#define KP 256
#define DK 64
#define MROWS (BB*TT)          // 16384
#define BHN (BB*HH)            // 64

typedef __half half_t;

// ---------------------------------------------------------------------------
// Scratch (static device globals; no allocation allowed)
// ---------------------------------------------------------------------------
__device__ half_t g_Ah[(size_t)MROWS * DD];      // x split hi (later ctx hi)
__device__ half_t g_Al[(size_t)MROWS * DD];      // x split lo (later ctx lo)
__device__ half_t g_Qh[(size_t)MROWS * DD];
__device__ half_t g_Ql[(size_t)MROWS * DD];
__device__ half_t g_Kh[(size_t)MROWS * DD];      // K split (exponent path)
__device__ half_t g_Kl[(size_t)MROWS * DD];
__device__ half_t g_V [(size_t)MROWS * DD];      // plain (linear path)
__device__ half_t g_Wt[4][(size_t)DD * DD];      // transposed [N][K] hi/plain
__device__ half_t g_Wlo[2][(size_t)DD * DD];     // Wq,Wk lo parts
__device__ half_t g_Eth[(size_t)2 * KP * TT];    // E^T split hi [z][kp][t]
__device__ half_t g_Etl[(size_t)2 * KP * TT];    // E^T split lo
__device__ half_t g_Kph[(size_t)BHN * KP * DK];  // Kp split (exponent path)
__device__ half_t g_Kpl[(size_t)BHN * KP * DK];
__device__ half_t g_Vp[(size_t)BHN * KP * DK];   // plain

// ---------------------------------------------------------------------------
// Helpers
// ---------------------------------------------------------------------------
__device__ __forceinline__ uint32_t smem_u32(const void* p) {
    uint32_t a;
    asm("{ .reg .u64 t; cvta.to.shared.u64 t, %1; cvt.u32.u64 %0, t; }" : "=r"(a) : "l"(p));
    return a;
}

#define CP_ASYNC16(dst, src) \
    asm volatile("cp.async.cg.shared.global [%0], [%1], 16;" :: "r"(dst), "l"(src))
#define CP_COMMIT() asm volatile("cp.async.commit_group;")
#define CP_WAIT1()  asm volatile("cp.async.wait_group 1;" ::: "memory")
#define CP_WAIT0()  asm volatile("cp.async.wait_group 0;" ::: "memory")

#define LDMATRIX_X4(r0, r1, r2, r3, addr) \
    asm volatile("ldmatrix.sync.aligned.m8n8.x4.shared.b16 {%0,%1,%2,%3}, [%4];" \
        : "=r"(r0), "=r"(r1), "=r"(r2), "=r"(r3) : "r"(addr))
#define LDMATRIX_X4_T(r0, r1, r2, r3, addr) \
    asm volatile("ldmatrix.sync.aligned.m8n8.x4.trans.shared.b16 {%0,%1,%2,%3}, [%4];" \
        : "=r"(r0), "=r"(r1), "=r"(r2), "=r"(r3) : "r"(addr))

#define MMA_F16(d, a, b0_, b1_) \
    asm volatile("mma.sync.aligned.m16n8k16.row.col.f32.f16.f16.f32 " \
        "{%0,%1,%2,%3},{%4,%5,%6,%7},{%8,%9},{%0,%1,%2,%3};" \
        : "+f"((d)[0]), "+f"((d)[1]), "+f"((d)[2]), "+f"((d)[3]) \
        : "r"((a)[0]), "r"((a)[1]), "r"((a)[2]), "r"((a)[3]), "r"(b0_), "r"(b1_))

__device__ __forceinline__ uint32_t pack_h2(float a, float b) {
    __half2 t = __floats2half2_rn(a, b);
    return *(uint32_t*)&t;
}
__device__ __forceinline__ void split2h(float a, float b, uint32_t& hi, uint32_t& lo) {
    __half2 h = __floats2half2_rn(a, b);
    hi = *(uint32_t*)&h;
    lo = pack_h2(a - __low2float(h), b - __high2float(h));
}

// ---------------------------------------------------------------------------
// Split fp32 -> fp16 hi/lo (vectorized x4)
// ---------------------------------------------------------------------------
__global__ __launch_bounds__(256) void split_kernel(
    const float* __restrict__ src, half_t* __restrict__ hi,
    half_t* __restrict__ lo, int n4)
{
    uint32_t* hi2 = (uint32_t*)hi;
    uint32_t* lo2 = (uint32_t*)lo;
    int stride = gridDim.x * blockDim.x;
    for (int i = blockIdx.x * blockDim.x + threadIdx.x; i < n4; i += stride) {
        float4 v = ((const float4*)src)[i];
        uint32_t h0, l0, h1, l1;
        split2h(v.x, v.y, h0, l0);
        split2h(v.z, v.w, h1, l1);
        hi2[2 * i + 0] = h0; hi2[2 * i + 1] = h1;
        lo2[2 * i + 0] = l0; lo2[2 * i + 1] = l1;
    }
}

// Transpose weights: z=0,1 (Wq,Wk) -> hi+lo split; z=2,3 (Wv,Wo) -> plain hi only
__global__ __launch_bounds__(256) void wconv_kernel(
    const float* __restrict__ W0, const float* __restrict__ W1,
    const float* __restrict__ W2, const float* __restrict__ W3,
    half_t* __restrict__ WtAll, half_t* __restrict__ WloAll)
{
    __shared__ float t[32][33];
    const int z = blockIdx.z;
    const float* W = (z == 0) ? W0 : (z == 1) ? W1 : (z == 2) ? W2 : W3;
    half_t* Wt = WtAll + (size_t)z * DD * DD;
    const int c0 = blockIdx.x * 32, r0 = blockIdx.y * 32;
    const int tx = threadIdx.x & 31, ty = threadIdx.x >> 5;
#pragma unroll
    for (int r = 0; r < 32; r += 8)
        t[ty + r][tx] = W[(size_t)(r0 + ty + r) * DD + c0 + tx];
    __syncthreads();
#pragma unroll
    for (int r = 0; r < 32; r += 8) {
        float v = t[tx][ty + r];
        half_t h = __float2half(v);
        size_t o = (size_t)(c0 + ty + r) * DD + r0 + tx;
        Wt[o] = h;
        if (z < 2)
            WloAll[(size_t)z * DD * DD + o] = __float2half(v - __half2float(h));
    }
}

// Transpose + split E (grid.z selects Ek/Ev): [T][KP] fp32 -> [KP][T] fp16 hi/lo
__global__ __launch_bounds__(256) void esplit_kernel(
    const float* __restrict__ E0, const float* __restrict__ E1,
    half_t* __restrict__ hiT, half_t* __restrict__ loT)
{
    __shared__ float t[32][33];
    const int z = blockIdx.z;
    const float* E = z ? E1 : E0;
    half_t* hi = hiT + (size_t)z * KP * TT;
    half_t* lo = loT + (size_t)z * KP * TT;
    const int c0 = blockIdx.x * 32, r0 = blockIdx.y * 32;
    const int tx = threadIdx.x & 31, ty = threadIdx.x >> 5;
#pragma unroll
    for (int r = 0; r < 32; r += 8)
        t[ty + r][tx] = E[(size_t)(r0 + ty + r) * KP + c0 + tx];
    __syncthreads();
#pragma unroll
    for (int r = 0; r < 32; r += 8) {
        float v = t[tx][ty + r];
        half_t h = __float2half(v);
        size_t o = (size_t)(c0 + ty + r) * TT + r0 + tx;
        hi[o] = h;
        lo[o] = __float2half(v - __half2float(h));
    }
}

// ---------------------------------------------------------------------------
// mma.sync fp16 GEMM: C = (Ah+Al)[M,K] * B^T
//   B split (3 MMAs) where (Bl != null && n0g < bl_cols), else plain (2 MMAs).
// Output modes: fp32 C (+bias); or QKV routing (Q split / K split / V plain).
// Block 128x128, K-chunk 32, 8 warps, 3-stage cp.async pipeline.
// ---------------------------------------------------------------------------
#define GTILE   10240                  // 128 rows * 80 B
#define GSTAGE  (4 * GTILE)            // AH, AL, BH, BL
#define TC_SMEM (3 * GSTAGE)           // 122880

__global__ __launch_bounds__(256) void tc_gemm(
    const half_t* __restrict__ Ah, const half_t* __restrict__ Al,
    const half_t* __restrict__ Bh, const half_t* __restrict__ Bl, int bl_cols,
    float* __restrict__ C, const float* __restrict__ bias,
    half_t* __restrict__ Qh, half_t* __restrict__ Ql,
    half_t* __restrict__ Kho, half_t* __restrict__ Klo,
    half_t* __restrict__ Vo, int Kn)
{
    extern __shared__ char smem[];
    const uint32_t sbase = smem_u32(smem);
    const int tid = threadIdx.x, wid = tid >> 5, lane = tid & 31;
    const int warp_m = wid >> 1, warp_n = wid & 1;
    const int m0 = blockIdx.y * 128;
    const int n0g = blockIdx.x * 128;
    const bool use_bl = (Bl != nullptr) && (n0g < bl_cols);

    float acc[2][8][4];
#pragma unroll
    for (int mt = 0; mt < 2; mt++)
#pragma unroll
        for (int nt = 0; nt < 8; nt++)
#pragma unroll
            for (int q = 0; q < 4; q++) acc[mt][nt][q] = 0.f;

    const uint32_t lofs = ((((lane >> 3) & 1) * 8 + (lane & 7)) * 80u) + ((lane >> 4) * 16u);
    const int ld_row0 = tid >> 2;
    const int ld_col  = tid & 3;

    const int NC = Kn >> 5;
#define LOAD_STAGE(s, k0v) do {                                                   \
        const uint32_t stg = sbase + (uint32_t)(s) * GSTAGE;                      \
        _Pragma("unroll")                                                         \
        for (int i = 0; i < 6; i++) {                                             \
            const int tile = i >> 1;                                              \
            const int row = (i & 1) * 64 + ld_row0;                               \
            const uint32_t dst = stg + tile * GTILE + row * 80 + ld_col * 16;     \
            const half_t* sp = (tile == 0 ? Ah : tile == 1 ? Al : Bh);            \
            const int grow = (tile < 2 ? m0 : n0g) + row;                         \
            CP_ASYNC16(dst, sp + (size_t)grow * Kn + (k0v) + ld_col * 8);         \
        }                                                                         \
        if (use_bl) {                                                             \
            _Pragma("unroll")                                                     \
            for (int i = 0; i < 2; i++) {                                         \
                const int row = i * 64 + ld_row0;                                 \
                const uint32_t dst = stg + 3 * GTILE + row * 80 + ld_col * 16;    \
                CP_ASYNC16(dst, Bl + (size_t)(n0g + row) * Kn + (k0v) + ld_col * 8); \
            }                                                                     \
        }                                                                         \
        CP_COMMIT();                                                              \
    } while (0)

    LOAD_STAGE(0, 0);
    LOAD_STAGE(1, 32);

    for (int c = 0; c < NC; c++) {
        const bool more = (c + 2 < NC);
        if (more) { CP_WAIT1(); } else { CP_WAIT0(); }   // tail: full drain (race fix)
        __syncthreads();
        if (more) LOAD_STAGE((c + 2) % 3, (c + 2) << 5);

        const uint32_t stg = sbase + (uint32_t)(c % 3) * GSTAGE;
        const uint32_t a_base = stg + (warp_m * 32) * 80 + lofs;
        const uint32_t b_base = stg + 2 * GTILE + (warp_n * 64) * 80 + lofs;

#pragma unroll
        for (int ks = 0; ks < 2; ks++) {
            uint32_t ah[2][4], al[2][4], b[4][4];
#pragma unroll
            for (int mt = 0; mt < 2; mt++) {
                LDMATRIX_X4(ah[mt][0], ah[mt][1], ah[mt][2], ah[mt][3],
                            a_base + mt * (16 * 80) + ks * 32);
                LDMATRIX_X4(al[mt][0], al[mt][1], al[mt][2], al[mt][3],
                            a_base + GTILE + mt * (16 * 80) + ks * 32);
            }
#pragma unroll
            for (int nq = 0; nq < 4; nq++)
                LDMATRIX_X4(b[nq][0], b[nq][1], b[nq][2], b[nq][3],
                            b_base + nq * (16 * 80) + ks * 32);
#pragma unroll
            for (int mt = 0; mt < 2; mt++)
#pragma unroll
                for (int nt = 0; nt < 8; nt++) {
                    const int nq = nt >> 1, sel = nt & 1;
                    MMA_F16(acc[mt][nt], ah[mt], b[nq][sel], b[nq][sel + 2]);
                    MMA_F16(acc[mt][nt], al[mt], b[nq][sel], b[nq][sel + 2]);
                }
            if (use_bl) {
#pragma unroll
                for (int nq = 0; nq < 4; nq++)
                    LDMATRIX_X4(b[nq][0], b[nq][1], b[nq][2], b[nq][3],
                                b_base + GTILE + nq * (16 * 80) + ks * 32);
#pragma unroll
                for (int mt = 0; mt < 2; mt++)
#pragma unroll
                    for (int nt = 0; nt < 8; nt++) {
                        const int nq = nt >> 1, sel = nt & 1;
                        MMA_F16(acc[mt][nt], ah[mt], b[nq][sel], b[nq][sel + 2]);
                    }
            }
        }
    }
#undef LOAD_STAGE

    const int g = lane >> 2, tig = lane & 3;
#pragma unroll
    for (int mt = 0; mt < 2; mt++) {
        const int row0 = m0 + warp_m * 32 + mt * 16 + g;
#pragma unroll
        for (int nt = 0; nt < 8; nt++) {
            const int colg = n0g + warp_n * 64 + nt * 8 + 2 * tig;
            if (C) {
                float bx = 0.f, by = 0.f;
                if (bias) { bx = bias[colg]; by = bias[colg + 1]; }
                *(float2*)(C + (size_t)row0 * DD + colg) =
                    make_float2(acc[mt][nt][0] + bx, acc[mt][nt][1] + by);
                *(float2*)(C + (size_t)(row0 + 8) * DD + colg) =
                    make_float2(acc[mt][nt][2] + bx, acc[mt][nt][3] + by);
            } else {
                const int which = colg >> 10;
                const int col = colg & 1023;
                const size_t o0 = (size_t)row0 * DD + col;
                const size_t o1 = (size_t)(row0 + 8) * DD + col;
                if (which == 2) {
                    *(uint32_t*)(Vo + o0) = pack_h2(acc[mt][nt][0], acc[mt][nt][1]);
                    *(uint32_t*)(Vo + o1) = pack_h2(acc[mt][nt][2], acc[mt][nt][3]);
                } else {
                    half_t* H = (which == 0) ? Qh : Kho;
                    half_t* L = (which == 0) ? Ql : Klo;
                    uint32_t hi, lo;
                    split2h(acc[mt][nt][0], acc[mt][nt][1], hi, lo);
                    *(uint32_t*)(H + o0) = hi; *(uint32_t*)(L + o0) = lo;
                    split2h(acc[mt][nt][2], acc[mt][nt][3], hi, lo);
                    *(uint32_t*)(H + o1) = hi; *(uint32_t*)(L + o1) = lo;
                }
            }
        }
    }
}

// ---------------------------------------------------------------------------
// Low-rank projection on MMA, 3-stage pipeline:
//   z=0: Kp = (Eh+El)^T * (Kh+Kl), 3 MMAs, split output (exponent path)
//   z=1: Vp = (Eh+El)^T * V,       2 MMAs, plain output
// grid = (KP/128, BHN, 2)
// ---------------------------------------------------------------------------
#define PAH 0
#define PALo 10240
#define PBH 20480
#define PBL (PBH + 32 * 144)
#define PSTAGE (PBL + 32 * 144)         // 29696
#define PROJ_SMEM (3 * PSTAGE)          // 89088

__global__ __launch_bounds__(256) void proj_mma(
    const half_t* __restrict__ Eh, const half_t* __restrict__ El,
    const half_t* __restrict__ Khp, const half_t* __restrict__ Klp,
    const half_t* __restrict__ Vb,
    half_t* __restrict__ Kph, half_t* __restrict__ Kpl,
    half_t* __restrict__ Vp)
{
    extern __shared__ char smem[];
    const uint32_t sbase = smem_u32(smem);
    const int tid = threadIdx.x, wid = tid >> 5, lane = tid & 31;
    const int m0k = blockIdx.x * 128;
    const int bh = blockIdx.y, z = blockIdx.z;
    const int b = bh >> 4, h = bh & 15;

    const half_t* Xh = z ? Vb : Khp;
    const half_t* Xl = Klp;            // used only when z==0
    const bool use_bl = (z == 0);
    const size_t eoff = (size_t)z * KP * TT;
    const size_t brow = (size_t)b * TT;
    const int hcol = h * 64;

    float cacc[8][4];
#pragma unroll
    for (int nt = 0; nt < 8; nt++)
#pragma unroll
        for (int q = 0; q < 4; q++) cacc[nt][q] = 0.f;

    const uint32_t lofsA = (lane & 15) * 80u + ((lane >> 4) * 16u);
    const uint32_t lofsB = (lane & 15) * 144u + ((lane >> 4) * 16u);
    const int wm = wid * 16;

#define PROJ_LOAD(s, k0v) do {                                                    \
        const uint32_t stg = sbase + (uint32_t)(s) * PSTAGE;                      \
        _Pragma("unroll")                                                         \
        for (int i = 0; i < 2; i++) {                                             \
            const int idx = tid + i * 256;                                        \
            const int r = idx >> 2, cc = idx & 3;                                 \
            const size_t gof = (size_t)(m0k + r) * TT + (k0v) + cc * 8;           \
            CP_ASYNC16(stg + PAH + r * 80 + cc * 16, Eh + eoff + gof);            \
            CP_ASYNC16(stg + PALo + r * 80 + cc * 16, El + eoff + gof);           \
        }                                                                         \
        {                                                                         \
            const int r = tid >> 3, cc = tid & 7;                                 \
            const size_t gof = (brow + (k0v) + r) * DD + hcol + cc * 8;           \
            CP_ASYNC16(stg + PBH + r * 144 + cc * 16, Xh + gof);                  \
            if (use_bl)                                                           \
                CP_ASYNC16(stg + PBL + r * 144 + cc * 16, Xl + gof);              \
        }                                                                         \
        CP_COMMIT();                                                              \
    } while (0)

    PROJ_LOAD(0, 0);
    PROJ_LOAD(1, 32);
    const int NC = TT >> 5;
    for (int c = 0; c < NC; c++) {
        const bool more = (c + 2 < NC);
        if (more) { CP_WAIT1(); } else { CP_WAIT0(); }   // tail: full drain
        __syncthreads();
        if (more) PROJ_LOAD((c + 2) % 3, (c + 2) << 5);

        const uint32_t stg = sbase + (uint32_t)(c % 3) * PSTAGE;
#pragma unroll
        for (int s = 0; s < 2; s++) {
            uint32_t ah[4], al[4], b4[4];
            LDMATRIX_X4(ah[0], ah[1], ah[2], ah[3], stg + PAH + wm * 80 + lofsA + s * 32);
            LDMATRIX_X4(al[0], al[1], al[2], al[3], stg + PALo + wm * 80 + lofsA + s * 32);
#pragma unroll
            for (int ng = 0; ng < 4; ng++) {
                LDMATRIX_X4_T(b4[0], b4[1], b4[2], b4[3],
                              stg + PBH + s * (16 * 144) + lofsB + ng * 32);
                MMA_F16(cacc[2 * ng], ah, b4[0], b4[1]);
                MMA_F16(cacc[2 * ng], al, b4[0], b4[1]);
                MMA_F16(cacc[2 * ng + 1], ah, b4[2], b4[3]);
                MMA_F16(cacc[2 * ng + 1], al, b4[2], b4[3]);
                if (use_bl) {
                    LDMATRIX_X4_T(b4[0], b4[1], b4[2], b4[3],
                                  stg + PBL + s * (16 * 144) + lofsB + ng * 32);
                    MMA_F16(cacc[2 * ng], ah, b4[0], b4[1]);
                    MMA_F16(cacc[2 * ng + 1], ah, b4[2], b4[3]);
                }
            }
        }
    }
#undef PROJ_LOAD

    const int g = lane >> 2, tig = lane & 3;
    const size_t obase = (size_t)bh * KP * DK;
#pragma unroll
    for (int nt = 0; nt < 8; nt++) {
        const int row0 = m0k + wm + g;
        const int col = nt * 8 + 2 * tig;
        const size_t o0 = obase + (size_t)row0 * DK + col;
        const size_t o1 = obase + (size_t)(row0 + 8) * DK + col;
        if (z == 0) {
            uint32_t hi, lo;
            split2h(cacc[nt][0], cacc[nt][1], hi, lo);
            *(uint32_t*)(Kph + o0) = hi; *(uint32_t*)(Kpl + o0) = lo;
            split2h(cacc[nt][2], cacc[nt][3], hi, lo);
            *(uint32_t*)(Kph + o1) = hi; *(uint32_t*)(Kpl + o1) = lo;
        } else {
            *(uint32_t*)(Vp + o0) = pack_h2(cacc[nt][0], cacc[nt][1]);
            *(uint32_t*)(Vp + o1) = pack_h2(cacc[nt][2], cacc[nt][3]);
        }
    }
}

// ---------------------------------------------------------------------------
// Fused MMA attention per (bh, 128-row t-tile):
//   S = (Qh+Ql)*(Kph+Kpl)^T   (3 MMAs — exponent path exact)
//   softmax on fragments; ctx = (Ph+Pl)*Vp (2 MMAs); ctx split to Ch/Cl.
// ---------------------------------------------------------------------------
#define AQH 0
#define AQL (AQH + 128 * 144)
#define AKH (AQL + 128 * 144)
#define AKL (AKH + 256 * 144)
#define AV  (AKL + 256 * 144)
#define ATTN_SMEM (AV + 256 * 144)      // 147456

__global__ __launch_bounds__(256) void attn_mma(
    const half_t* __restrict__ Qh, const half_t* __restrict__ Ql,
    const half_t* __restrict__ Kp, const half_t* __restrict__ Kpl,
    const half_t* __restrict__ Vp,
    half_t* __restrict__ Ch, half_t* __restrict__ Cl)
{
    extern __shared__ char smem[];
    const uint32_t sbase = smem_u32(smem);
    const int tid = threadIdx.x, wid = tid >> 5, lane = tid & 31;
    const int bh = blockIdx.y, b = bh >> 4, h = bh & 15;
    const int t0 = blockIdx.x * 128;

    const size_t qbase = (size_t)(b * TT + t0) * DD + h * 64;
    for (int idx = tid; idx < 128 * 8; idx += 256) {
        const int r = idx >> 3, c = idx & 7;
        const size_t go = qbase + (size_t)r * DD + c * 8;
        *(uint4*)(smem + AQH + r * 144 + c * 16) = *(const uint4*)(Qh + go);
        *(uint4*)(smem + AQL + r * 144 + c * 16) = *(const uint4*)(Ql + go);
    }
    const size_t kpb = (size_t)bh * KP * DK;
    for (int idx = tid; idx < 256 * 8; idx += 256) {
        const int r = idx >> 3, c = idx & 7;
        const size_t go = kpb + (size_t)r * DK + c * 8;
        *(uint4*)(smem + AKH + r * 144 + c * 16) = *(const uint4*)(Kp + go);
        *(uint4*)(smem + AKL + r * 144 + c * 16) = *(const uint4*)(Kpl + go);
        *(uint4*)(smem + AV + r * 144 + c * 16) = *(const uint4*)(Vp + go);
    }
    __syncthreads();

    const int wm = wid * 16;
    const uint32_t lofs = (lane & 15) * 144u + ((lane >> 4) * 16u);

    // --- scores (3-term) ---
    float sacc[32][4];
#pragma unroll
    for (int j = 0; j < 32; j++)
#pragma unroll
        for (int q = 0; q < 4; q++) sacc[j][q] = 0.f;

#pragma unroll
    for (int s = 0; s < 4; s++) {
        uint32_t qh4[4], ql4[4], b4[4];
        LDMATRIX_X4(qh4[0], qh4[1], qh4[2], qh4[3], sbase + AQH + wm * 144 + lofs + s * 32);
        LDMATRIX_X4(ql4[0], ql4[1], ql4[2], ql4[3], sbase + AQL + wm * 144 + lofs + s * 32);
#pragma unroll
        for (int ng = 0; ng < 16; ng++) {
            LDMATRIX_X4(b4[0], b4[1], b4[2], b4[3],
                        sbase + AKH + ng * (16 * 144) + lofs + s * 32);
            MMA_F16(sacc[2 * ng], qh4, b4[0], b4[2]);
            MMA_F16(sacc[2 * ng], ql4, b4[0], b4[2]);
            MMA_F16(sacc[2 * ng + 1], qh4, b4[1], b4[3]);
            MMA_F16(sacc[2 * ng + 1], ql4, b4[1], b4[3]);
            LDMATRIX_X4(b4[0], b4[1], b4[2], b4[3],
                        sbase + AKL + ng * (16 * 144) + lofs + s * 32);
            MMA_F16(sacc[2 * ng], qh4, b4[0], b4[2]);
            MMA_F16(sacc[2 * ng + 1], qh4, b4[1], b4[3]);
        }
    }

    // --- softmax on fragments ---
    float m0 = -1e30f, m1 = -1e30f;
#pragma unroll
    for (int j = 0; j < 32; j++) {
        m0 = fmaxf(m0, fmaxf(sacc[j][0], sacc[j][1]));
        m1 = fmaxf(m1, fmaxf(sacc[j][2], sacc[j][3]));
    }
    m0 = fmaxf(m0, __shfl_xor_sync(0xffffffffu, m0, 1));
    m0 = fmaxf(m0, __shfl_xor_sync(0xffffffffu, m0, 2));
    m1 = fmaxf(m1, __shfl_xor_sync(0xffffffffu, m1, 1));
    m1 = fmaxf(m1, __shfl_xor_sync(0xffffffffu, m1, 2));

    float sum0 = 0.f, sum1 = 0.f;
#pragma unroll
    for (int j = 0; j < 32; j++) {
        float e0 = __expf((sacc[j][0] - m0) * 0.125f);
        float e1 = __expf((sacc[j][1] - m0) * 0.125f);
        float e2 = __expf((sacc[j][2] - m1) * 0.125f);
        float e3 = __expf((sacc[j][3] - m1) * 0.125f);
        sacc[j][0] = e0; sacc[j][1] = e1; sacc[j][2] = e2; sacc[j][3] = e3;
        sum0 += e0 + e1; sum1 += e2 + e3;
    }
    sum0 += __shfl_xor_sync(0xffffffffu, sum0, 1);
    sum0 += __shfl_xor_sync(0xffffffffu, sum0, 2);
    sum1 += __shfl_xor_sync(0xffffffffu, sum1, 1);
    sum1 += __shfl_xor_sync(0xffffffffu, sum1, 2);
    const float inv0 = __frcp_rn(sum0), inv1 = __frcp_rn(sum1);

    // --- ctx = P * Vp (2-term, P split in-register) ---
    float cacc[8][4];
#pragma unroll
    for (int nt = 0; nt < 8; nt++)
#pragma unroll
        for (int q = 0; q < 4; q++) cacc[nt][q] = 0.f;

#pragma unroll
    for (int s = 0; s < 16; s++) {
        uint32_t ah4[4], al4[4], b4[4];
        split2h(sacc[2 * s][0],     sacc[2 * s][1],     ah4[0], al4[0]);
        split2h(sacc[2 * s][2],     sacc[2 * s][3],     ah4[1], al4[1]);
        split2h(sacc[2 * s + 1][0], sacc[2 * s + 1][1], ah4[2], al4[2]);
        split2h(sacc[2 * s + 1][2], sacc[2 * s + 1][3], ah4[3], al4[3]);
#pragma unroll
        for (int ng = 0; ng < 4; ng++) {
            LDMATRIX_X4_T(b4[0], b4[1], b4[2], b4[3],
                          sbase + AV + s * (16 * 144) + lofs + ng * 32);
            MMA_F16(cacc[2 * ng], ah4, b4[0], b4[1]);
            MMA_F16(cacc[2 * ng], al4, b4[0], b4[1]);
            MMA_F16(cacc[2 * ng + 1], ah4, b4[2], b4[3]);
            MMA_F16(cacc[2 * ng + 1], al4, b4[2], b4[3]);
        }
    }

    const int g = lane >> 2, tig = lane & 3;
    const size_t r0 = (size_t)(b * TT + t0 + wm + g) * DD + h * 64;
    const size_t r1 = r0 + 8 * DD;
#pragma unroll
    for (int nt = 0; nt < 8; nt++) {
        const int col = nt * 8 + 2 * tig;
        uint32_t hi, lo;
        split2h(cacc[nt][0] * inv0, cacc[nt][1] * inv0, hi, lo);
        *(uint32_t*)(Ch + r0 + col) = hi;
        *(uint32_t*)(Cl + r0 + col) = lo;
        split2h(cacc[nt][2] * inv1, cacc[nt][3] * inv1, hi, lo);
        *(uint32_t*)(Ch + r1 + col) = hi;
        *(uint32_t*)(Cl + r1 + col) = lo;
    }
}

// ---------------------------------------------------------------------------
// Launch
// ---------------------------------------------------------------------------
extern "C" void kernel_launch(void* const* d_in, const int* in_sizes, int n_in,
                              void* d_out, int out_size)
{
    const float* x  = (const float*)d_in[0];
    const float* Wq = (const float*)d_in[1];
    const float* Wk = (const float*)d_in[2];
    const float* Wv = (const float*)d_in[3];
    const float* Ek = (const float*)d_in[4];
    const float* Ev = (const float*)d_in[5];
    const float* Wo = (const float*)d_in[6];
    const float* bo = (const float*)d_in[7];
    float* out = (float*)d_out;

    half_t *Ahp, *Alp, *Qhp, *Qlp, *Khp, *Klp, *Vbp, *Wtp, *Wlop;
    half_t *Ethp, *Etlp, *Kphp, *Kplp, *Vpp;
    cudaGetSymbolAddress((void**)&Ahp, g_Ah);
    cudaGetSymbolAddress((void**)&Alp, g_Al);
    cudaGetSymbolAddress((void**)&Qhp, g_Qh);
    cudaGetSymbolAddress((void**)&Qlp, g_Ql);
    cudaGetSymbolAddress((void**)&Khp, g_Kh);
    cudaGetSymbolAddress((void**)&Klp, g_Kl);
    cudaGetSymbolAddress((void**)&Vbp, g_V);
    cudaGetSymbolAddress((void**)&Wtp, g_Wt);
    cudaGetSymbolAddress((void**)&Wlop, g_Wlo);
    cudaGetSymbolAddress((void**)&Ethp, g_Eth);
    cudaGetSymbolAddress((void**)&Etlp, g_Etl);
    cudaGetSymbolAddress((void**)&Kphp, g_Kph);
    cudaGetSymbolAddress((void**)&Kplp, g_Kpl);
    cudaGetSymbolAddress((void**)&Vpp, g_Vp);

    const size_t WSZ = (size_t)DD * DD;

    cudaFuncSetAttribute(tc_gemm, cudaFuncAttributeMaxDynamicSharedMemorySize, TC_SMEM);
    cudaFuncSetAttribute(proj_mma, cudaFuncAttributeMaxDynamicSharedMemorySize, PROJ_SMEM);
    cudaFuncSetAttribute(attn_mma, cudaFuncAttributeMaxDynamicSharedMemorySize, ATTN_SMEM);

    // 1) split x -> fp16 hi/lo
    split_kernel<<<2048, 256>>>(x, Ahp, Alp, MROWS * DD / 4);
    // 2) transpose weights (Wq,Wk split; Wv,Wo plain) + split E
    wconv_kernel<<<dim3(DD / 32, DD / 32, 4), 256>>>(Wq, Wk, Wv, Wo, Wtp, Wlop);
    esplit_kernel<<<dim3(KP / 32, TT / 32, 2), 256>>>(Ek, Ev, Ethp, Etlp);

    // 3) fused QKV: B hi = [WqT|WkT|WvT], B lo = [Wq_lo|Wk_lo] (first 2048 cols 3-term)
    tc_gemm<<<dim3(3 * DD / 128, MROWS / 128), 256, TC_SMEM>>>(
        Ahp, Alp, Wtp, Wlop, 2 * DD, nullptr, nullptr,
        Qhp, Qlp, Khp, Klp, Vbp, DD);

    // 4) low-rank projections (z=0: Kp 3-term split out; z=1: Vp 2-term plain)
    proj_mma<<<dim3(KP / 128, BHN, 2), 256, PROJ_SMEM>>>(
        Ethp, Etlp, Khp, Klp, Vbp, Kphp, Kplp, Vpp);

    // 5) fused attention -> ctx split into Ah/Al
    attn_mma<<<dim3(TT / 128, BHN), 256, ATTN_SMEM>>>(
        Qhp, Qlp, Kphp, Kplp, Vpp, Ahp, Alp);

    // 6) output projection + bias (2-term, fp32 out)
    tc_gemm<<<dim3(DD / 128, MROWS / 128), 256, TC_SMEM>>>(
        Ahp, Alp, Wtp + 3 * WSZ, nullptr, 0, out, bo,
        nullptr, nullptr, nullptr, nullptr, nullptr, DD);
}

// round 8
// speedup vs baseline: 1.2861x; 1.2861x over previous
#include <cuda_runtime.h>
#include <cuda_fp16.h>
#include <cstdint>
#include <math.h>

// Problem constants
#define BB 4
#define TT 4096
#define DD 1024
#define HH 16
#define KP 256
#define DK 64
#define MROWS (BB*TT)          // 16384
#define BHN (BB*HH)            // 64

typedef __half half_t;

// ---------------------------------------------------------------------------
// Scratch (static device globals; no allocation allowed)
// ---------------------------------------------------------------------------
__device__ half_t g_Ah[(size_t)MROWS * DD];      // x split hi (later ctx hi)
__device__ half_t g_Al[(size_t)MROWS * DD];      // x split lo (later ctx lo)
__device__ half_t g_Qh[(size_t)MROWS * DD];
__device__ half_t g_Ql[(size_t)MROWS * DD];
__device__ half_t g_Kh[(size_t)MROWS * DD];      // K split (exponent path)
__device__ half_t g_Kl[(size_t)MROWS * DD];
__device__ half_t g_V [(size_t)MROWS * DD];      // plain (linear path)
__device__ half_t g_Wt[4][(size_t)DD * DD];      // transposed [N][K], plain
__device__ half_t g_Eth[(size_t)2 * KP * TT];    // E^T split hi [z][kp][t]
__device__ half_t g_Etl[(size_t)2 * KP * TT];    // E^T split lo
__device__ half_t g_Kph[(size_t)BHN * KP * DK];  // Kp split (exponent path)
__device__ half_t g_Kpl[(size_t)BHN * KP * DK];
__device__ half_t g_Vp[(size_t)BHN * KP * DK];   // plain

// ---------------------------------------------------------------------------
// Helpers
// ---------------------------------------------------------------------------
__device__ __forceinline__ uint32_t smem_u32(const void* p) {
    uint32_t a;
    asm("{ .reg .u64 t; cvta.to.shared.u64 t, %1; cvt.u32.u64 %0, t; }" : "=r"(a) : "l"(p));
    return a;
}

#define CP_ASYNC16(dst, src) \
    asm volatile("cp.async.cg.shared.global [%0], [%1], 16;" :: "r"(dst), "l"(src))
#define CP_COMMIT() asm volatile("cp.async.commit_group;")
#define CP_WAIT1()  asm volatile("cp.async.wait_group 1;" ::: "memory")
#define CP_WAIT0()  asm volatile("cp.async.wait_group 0;" ::: "memory")

#define LDMATRIX_X4(r0, r1, r2, r3, addr) \
    asm volatile("ldmatrix.sync.aligned.m8n8.x4.shared.b16 {%0,%1,%2,%3}, [%4];" \
        : "=r"(r0), "=r"(r1), "=r"(r2), "=r"(r3) : "r"(addr))
#define LDMATRIX_X4_T(r0, r1, r2, r3, addr) \
    asm volatile("ldmatrix.sync.aligned.m8n8.x4.trans.shared.b16 {%0,%1,%2,%3}, [%4];" \
        : "=r"(r0), "=r"(r1), "=r"(r2), "=r"(r3) : "r"(addr))

#define MMA_F16(d, a, b0_, b1_) \
    asm volatile("mma.sync.aligned.m16n8k16.row.col.f32.f16.f16.f32 " \
        "{%0,%1,%2,%3},{%4,%5,%6,%7},{%8,%9},{%0,%1,%2,%3};" \
        : "+f"((d)[0]), "+f"((d)[1]), "+f"((d)[2]), "+f"((d)[3]) \
        : "r"((a)[0]), "r"((a)[1]), "r"((a)[2]), "r"((a)[3]), "r"(b0_), "r"(b1_))

__device__ __forceinline__ uint32_t pack_h2(float a, float b) {
    __half2 t = __floats2half2_rn(a, b);
    return *(uint32_t*)&t;
}
__device__ __forceinline__ void split2h(float a, float b, uint32_t& hi, uint32_t& lo) {
    __half2 h = __floats2half2_rn(a, b);
    hi = *(uint32_t*)&h;
    lo = pack_h2(a - __low2float(h), b - __high2float(h));
}

// ---------------------------------------------------------------------------
// Split fp32 -> fp16 hi/lo (vectorized x4)
// ---------------------------------------------------------------------------
__global__ __launch_bounds__(256) void split_kernel(
    const float* __restrict__ src, half_t* __restrict__ hi,
    half_t* __restrict__ lo, int n4)
{
    uint32_t* hi2 = (uint32_t*)hi;
    uint32_t* lo2 = (uint32_t*)lo;
    int stride = gridDim.x * blockDim.x;
    for (int i = blockIdx.x * blockDim.x + threadIdx.x; i < n4; i += stride) {
        float4 v = ((const float4*)src)[i];
        uint32_t h0, l0, h1, l1;
        split2h(v.x, v.y, h0, l0);
        split2h(v.z, v.w, h1, l1);
        hi2[2 * i + 0] = h0; hi2[2 * i + 1] = h1;
        lo2[2 * i + 0] = l0; lo2[2 * i + 1] = l1;
    }
}

// Transpose + convert all 4 weights (grid.z selects): [D][D] fp32 -> [N][K] fp16
__global__ __launch_bounds__(256) void wconv_kernel(
    const float* __restrict__ W0, const float* __restrict__ W1,
    const float* __restrict__ W2, const float* __restrict__ W3,
    half_t* __restrict__ WtAll)
{
    __shared__ float t[32][33];
    const int z = blockIdx.z;
    const float* W = (z == 0) ? W0 : (z == 1) ? W1 : (z == 2) ? W2 : W3;
    half_t* Wt = WtAll + (size_t)z * DD * DD;
    const int c0 = blockIdx.x * 32, r0 = blockIdx.y * 32;
    const int tx = threadIdx.x & 31, ty = threadIdx.x >> 5;
#pragma unroll
    for (int r = 0; r < 32; r += 8)
        t[ty + r][tx] = W[(size_t)(r0 + ty + r) * DD + c0 + tx];
    __syncthreads();
#pragma unroll
    for (int r = 0; r < 32; r += 8)
        Wt[(size_t)(c0 + ty + r) * DD + r0 + tx] = __float2half(t[tx][ty + r]);
}

// Transpose + split E (grid.z selects Ek/Ev): [T][KP] fp32 -> [KP][T] fp16 hi/lo
__global__ __launch_bounds__(256) void esplit_kernel(
    const float* __restrict__ E0, const float* __restrict__ E1,
    half_t* __restrict__ hiT, half_t* __restrict__ loT)
{
    __shared__ float t[32][33];
    const int z = blockIdx.z;
    const float* E = z ? E1 : E0;
    half_t* hi = hiT + (size_t)z * KP * TT;
    half_t* lo = loT + (size_t)z * KP * TT;
    const int c0 = blockIdx.x * 32, r0 = blockIdx.y * 32;
    const int tx = threadIdx.x & 31, ty = threadIdx.x >> 5;
#pragma unroll
    for (int r = 0; r < 32; r += 8)
        t[ty + r][tx] = E[(size_t)(r0 + ty + r) * KP + c0 + tx];
    __syncthreads();
#pragma unroll
    for (int r = 0; r < 32; r += 8) {
        float v = t[tx][ty + r];
        half_t h = __float2half(v);
        size_t o = (size_t)(c0 + ty + r) * TT + r0 + tx;
        hi[o] = h;
        lo[o] = __float2half(v - __half2float(h));
    }
}

// ---------------------------------------------------------------------------
// mma.sync fp16 GEMM: C = (Ah+Al)[M,K] * B^T  (B plain, 2 MMAs/tile)
// Output modes: fp32 C (+bias); or QKV routing (Q split / K split / V plain).
// Block 128x128, K-chunk 32, 8 warps, 3-stage cp.async pipeline, 2 CTAs/SM.
// ---------------------------------------------------------------------------
#define GTILE   10240                  // 128 rows * 80 B
#define GSTAGE  (3 * GTILE)            // AH, AL, B
#define TC_SMEM (3 * GSTAGE)           // 92160

__global__ __launch_bounds__(256, 2) void tc_gemm(
    const half_t* __restrict__ Ah, const half_t* __restrict__ Al,
    const half_t* __restrict__ Bh,
    float* __restrict__ C, const float* __restrict__ bias,
    half_t* __restrict__ Qh, half_t* __restrict__ Ql,
    half_t* __restrict__ Kho, half_t* __restrict__ Klo,
    half_t* __restrict__ Vo, int Kn)
{
    extern __shared__ char smem[];
    const uint32_t sbase = smem_u32(smem);
    const int tid = threadIdx.x, wid = tid >> 5, lane = tid & 31;
    const int warp_m = wid >> 1, warp_n = wid & 1;
    const int m0 = blockIdx.y * 128;
    const int n0g = blockIdx.x * 128;

    float acc[2][8][4];
#pragma unroll
    for (int mt = 0; mt < 2; mt++)
#pragma unroll
        for (int nt = 0; nt < 8; nt++)
#pragma unroll
            for (int q = 0; q < 4; q++) acc[mt][nt][q] = 0.f;

    const uint32_t lofs = ((((lane >> 3) & 1) * 8 + (lane & 7)) * 80u) + ((lane >> 4) * 16u);
    const int ld_row0 = tid >> 2;
    const int ld_col  = tid & 3;

    const int NC = Kn >> 5;
#define LOAD_STAGE(s, k0v) do {                                                   \
        const uint32_t stg = sbase + (uint32_t)(s) * GSTAGE;                      \
        _Pragma("unroll")                                                         \
        for (int i = 0; i < 6; i++) {                                             \
            const int tile = i >> 1;                                              \
            const int row = (i & 1) * 64 + ld_row0;                               \
            const uint32_t dst = stg + tile * GTILE + row * 80 + ld_col * 16;     \
            const half_t* sp = (tile == 0 ? Ah : tile == 1 ? Al : Bh);            \
            const int grow = (tile < 2 ? m0 : n0g) + row;                         \
            CP_ASYNC16(dst, sp + (size_t)grow * Kn + (k0v) + ld_col * 8);         \
        }                                                                         \
        CP_COMMIT();                                                              \
    } while (0)

    LOAD_STAGE(0, 0);
    LOAD_STAGE(1, 32);

    for (int c = 0; c < NC; c++) {
        const bool more = (c + 2 < NC);
        if (more) { CP_WAIT1(); } else { CP_WAIT0(); }   // tail: full drain
        __syncthreads();
        if (more) LOAD_STAGE((c + 2) % 3, (c + 2) << 5);

        const uint32_t stg = sbase + (uint32_t)(c % 3) * GSTAGE;
        const uint32_t a_base = stg + (warp_m * 32) * 80 + lofs;
        const uint32_t b_base = stg + 2 * GTILE + (warp_n * 64) * 80 + lofs;

#pragma unroll
        for (int ks = 0; ks < 2; ks++) {
            uint32_t ah[2][4], al[2][4], b[4][4];
#pragma unroll
            for (int mt = 0; mt < 2; mt++) {
                LDMATRIX_X4(ah[mt][0], ah[mt][1], ah[mt][2], ah[mt][3],
                            a_base + mt * (16 * 80) + ks * 32);
                LDMATRIX_X4(al[mt][0], al[mt][1], al[mt][2], al[mt][3],
                            a_base + GTILE + mt * (16 * 80) + ks * 32);
            }
#pragma unroll
            for (int nq = 0; nq < 4; nq++)
                LDMATRIX_X4(b[nq][0], b[nq][1], b[nq][2], b[nq][3],
                            b_base + nq * (16 * 80) + ks * 32);
#pragma unroll
            for (int mt = 0; mt < 2; mt++)
#pragma unroll
                for (int nt = 0; nt < 8; nt++) {
                    const int nq = nt >> 1, sel = nt & 1;
                    MMA_F16(acc[mt][nt], ah[mt], b[nq][sel], b[nq][sel + 2]);
                    MMA_F16(acc[mt][nt], al[mt], b[nq][sel], b[nq][sel + 2]);
                }
        }
    }
#undef LOAD_STAGE

    const int g = lane >> 2, tig = lane & 3;
#pragma unroll
    for (int mt = 0; mt < 2; mt++) {
        const int row0 = m0 + warp_m * 32 + mt * 16 + g;
#pragma unroll
        for (int nt = 0; nt < 8; nt++) {
            const int colg = n0g + warp_n * 64 + nt * 8 + 2 * tig;
            if (C) {
                float bx = 0.f, by = 0.f;
                if (bias) { bx = bias[colg]; by = bias[colg + 1]; }
                *(float2*)(C + (size_t)row0 * DD + colg) =
                    make_float2(acc[mt][nt][0] + bx, acc[mt][nt][1] + by);
                *(float2*)(C + (size_t)(row0 + 8) * DD + colg) =
                    make_float2(acc[mt][nt][2] + bx, acc[mt][nt][3] + by);
            } else {
                const int which = colg >> 10;
                const int col = colg & 1023;
                const size_t o0 = (size_t)row0 * DD + col;
                const size_t o1 = (size_t)(row0 + 8) * DD + col;
                if (which == 2) {
                    *(uint32_t*)(Vo + o0) = pack_h2(acc[mt][nt][0], acc[mt][nt][1]);
                    *(uint32_t*)(Vo + o1) = pack_h2(acc[mt][nt][2], acc[mt][nt][3]);
                } else {
                    half_t* H = (which == 0) ? Qh : Kho;
                    half_t* L = (which == 0) ? Ql : Klo;
                    uint32_t hi, lo;
                    split2h(acc[mt][nt][0], acc[mt][nt][1], hi, lo);
                    *(uint32_t*)(H + o0) = hi; *(uint32_t*)(L + o0) = lo;
                    split2h(acc[mt][nt][2], acc[mt][nt][3], hi, lo);
                    *(uint32_t*)(H + o1) = hi; *(uint32_t*)(L + o1) = lo;
                }
            }
        }
    }
}

// ---------------------------------------------------------------------------
// Low-rank projection on MMA, 3-stage pipeline:
//   z=0: Kp = (Eh+El)^T * (Kh+Kl), 3 MMAs, split output (exponent path)
//   z=1: Vp = (Eh+El)^T * V,       2 MMAs, plain output
// grid = (KP/128, BHN, 2)
// ---------------------------------------------------------------------------
#define PAH 0
#define PALo 10240
#define PBH 20480
#define PBL (PBH + 32 * 144)
#define PSTAGE (PBL + 32 * 144)         // 29696
#define PROJ_SMEM (3 * PSTAGE)          // 89088

__global__ __launch_bounds__(256) void proj_mma(
    const half_t* __restrict__ Eh, const half_t* __restrict__ El,
    const half_t* __restrict__ Khp, const half_t* __restrict__ Klp,
    const half_t* __restrict__ Vb,
    half_t* __restrict__ Kph, half_t* __restrict__ Kpl,
    half_t* __restrict__ Vp)
{
    extern __shared__ char smem[];
    const uint32_t sbase = smem_u32(smem);
    const int tid = threadIdx.x, wid = tid >> 5, lane = tid & 31;
    const int m0k = blockIdx.x * 128;
    const int bh = blockIdx.y, z = blockIdx.z;
    const int b = bh >> 4, h = bh & 15;

    const half_t* Xh = z ? Vb : Khp;
    const half_t* Xl = Klp;            // used only when z==0
    const bool use_bl = (z == 0);
    const size_t eoff = (size_t)z * KP * TT;
    const size_t brow = (size_t)b * TT;
    const int hcol = h * 64;

    float cacc[8][4];
#pragma unroll
    for (int nt = 0; nt < 8; nt++)
#pragma unroll
        for (int q = 0; q < 4; q++) cacc[nt][q] = 0.f;

    const uint32_t lofsA = (lane & 15) * 80u + ((lane >> 4) * 16u);
    const uint32_t lofsB = (lane & 15) * 144u + ((lane >> 4) * 16u);
    const int wm = wid * 16;

#define PROJ_LOAD(s, k0v) do {                                                    \
        const uint32_t stg = sbase + (uint32_t)(s) * PSTAGE;                      \
        _Pragma("unroll")                                                         \
        for (int i = 0; i < 2; i++) {                                             \
            const int idx = tid + i * 256;                                        \
            const int r = idx >> 2, cc = idx & 3;                                 \
            const size_t gof = (size_t)(m0k + r) * TT + (k0v) + cc * 8;           \
            CP_ASYNC16(stg + PAH + r * 80 + cc * 16, Eh + eoff + gof);            \
            CP_ASYNC16(stg + PALo + r * 80 + cc * 16, El + eoff + gof);           \
        }                                                                         \
        {                                                                         \
            const int r = tid >> 3, cc = tid & 7;                                 \
            const size_t gof = (brow + (k0v) + r) * DD + hcol + cc * 8;           \
            CP_ASYNC16(stg + PBH + r * 144 + cc * 16, Xh + gof);                  \
            if (use_bl)                                                           \
                CP_ASYNC16(stg + PBL + r * 144 + cc * 16, Xl + gof);              \
        }                                                                         \
        CP_COMMIT();                                                              \
    } while (0)

    PROJ_LOAD(0, 0);
    PROJ_LOAD(1, 32);
    const int NC = TT >> 5;
    for (int c = 0; c < NC; c++) {
        const bool more = (c + 2 < NC);
        if (more) { CP_WAIT1(); } else { CP_WAIT0(); }   // tail: full drain
        __syncthreads();
        if (more) PROJ_LOAD((c + 2) % 3, (c + 2) << 5);

        const uint32_t stg = sbase + (uint32_t)(c % 3) * PSTAGE;
#pragma unroll
        for (int s = 0; s < 2; s++) {
            uint32_t ah[4], al[4], b4[4];
            LDMATRIX_X4(ah[0], ah[1], ah[2], ah[3], stg + PAH + wm * 80 + lofsA + s * 32);
            LDMATRIX_X4(al[0], al[1], al[2], al[3], stg + PALo + wm * 80 + lofsA + s * 32);
#pragma unroll
            for (int ng = 0; ng < 4; ng++) {
                LDMATRIX_X4_T(b4[0], b4[1], b4[2], b4[3],
                              stg + PBH + s * (16 * 144) + lofsB + ng * 32);
                MMA_F16(cacc[2 * ng], ah, b4[0], b4[1]);
                MMA_F16(cacc[2 * ng], al, b4[0], b4[1]);
                MMA_F16(cacc[2 * ng + 1], ah, b4[2], b4[3]);
                MMA_F16(cacc[2 * ng + 1], al, b4[2], b4[3]);
                if (use_bl) {
                    LDMATRIX_X4_T(b4[0], b4[1], b4[2], b4[3],
                                  stg + PBL + s * (16 * 144) + lofsB + ng * 32);
                    MMA_F16(cacc[2 * ng], ah, b4[0], b4[1]);
                    MMA_F16(cacc[2 * ng + 1], ah, b4[2], b4[3]);
                }
            }
        }
    }
#undef PROJ_LOAD

    const int g = lane >> 2, tig = lane & 3;
    const size_t obase = (size_t)bh * KP * DK;
#pragma unroll
    for (int nt = 0; nt < 8; nt++) {
        const int row0 = m0k + wm + g;
        const int col = nt * 8 + 2 * tig;
        const size_t o0 = obase + (size_t)row0 * DK + col;
        const size_t o1 = obase + (size_t)(row0 + 8) * DK + col;
        if (z == 0) {
            uint32_t hi, lo;
            split2h(cacc[nt][0], cacc[nt][1], hi, lo);
            *(uint32_t*)(Kph + o0) = hi; *(uint32_t*)(Kpl + o0) = lo;
            split2h(cacc[nt][2], cacc[nt][3], hi, lo);
            *(uint32_t*)(Kph + o1) = hi; *(uint32_t*)(Kpl + o1) = lo;
        } else {
            *(uint32_t*)(Vp + o0) = pack_h2(cacc[nt][0], cacc[nt][1]);
            *(uint32_t*)(Vp + o1) = pack_h2(cacc[nt][2], cacc[nt][3]);
        }
    }
}

// ---------------------------------------------------------------------------
// Fused MMA attention per (bh, 128-row t-tile):
//   S = (Qh+Ql)*(Kph+Kpl)^T   (3 MMAs — exponent path exact)
//   softmax on fragments; ctx = (Ph+Pl)*Vp (2 MMAs); ctx split to Ch/Cl.
// ---------------------------------------------------------------------------
#define AQH 0
#define AQL (AQH + 128 * 144)
#define AKH (AQL + 128 * 144)
#define AKL (AKH + 256 * 144)
#define AV  (AKL + 256 * 144)
#define ATTN_SMEM (AV + 256 * 144)      // 147456

__global__ __launch_bounds__(256) void attn_mma(
    const half_t* __restrict__ Qh, const half_t* __restrict__ Ql,
    const half_t* __restrict__ Kp, const half_t* __restrict__ Kpl,
    const half_t* __restrict__ Vp,
    half_t* __restrict__ Ch, half_t* __restrict__ Cl)
{
    extern __shared__ char smem[];
    const uint32_t sbase = smem_u32(smem);
    const int tid = threadIdx.x, wid = tid >> 5, lane = tid & 31;
    const int bh = blockIdx.y, b = bh >> 4, h = bh & 15;
    const int t0 = blockIdx.x * 128;

    const size_t qbase = (size_t)(b * TT + t0) * DD + h * 64;
    for (int idx = tid; idx < 128 * 8; idx += 256) {
        const int r = idx >> 3, c = idx & 7;
        const size_t go = qbase + (size_t)r * DD + c * 8;
        *(uint4*)(smem + AQH + r * 144 + c * 16) = *(const uint4*)(Qh + go);
        *(uint4*)(smem + AQL + r * 144 + c * 16) = *(const uint4*)(Ql + go);
    }
    const size_t kpb = (size_t)bh * KP * DK;
    for (int idx = tid; idx < 256 * 8; idx += 256) {
        const int r = idx >> 3, c = idx & 7;
        const size_t go = kpb + (size_t)r * DK + c * 8;
        *(uint4*)(smem + AKH + r * 144 + c * 16) = *(const uint4*)(Kp + go);
        *(uint4*)(smem + AKL + r * 144 + c * 16) = *(const uint4*)(Kpl + go);
        *(uint4*)(smem + AV + r * 144 + c * 16) = *(const uint4*)(Vp + go);
    }
    __syncthreads();

    const int wm = wid * 16;
    const uint32_t lofs = (lane & 15) * 144u + ((lane >> 4) * 16u);

    // --- scores (3-term) ---
    float sacc[32][4];
#pragma unroll
    for (int j = 0; j < 32; j++)
#pragma unroll
        for (int q = 0; q < 4; q++) sacc[j][q] = 0.f;

#pragma unroll
    for (int s = 0; s < 4; s++) {
        uint32_t qh4[4], ql4[4], b4[4];
        LDMATRIX_X4(qh4[0], qh4[1], qh4[2], qh4[3], sbase + AQH + wm * 144 + lofs + s * 32);
        LDMATRIX_X4(ql4[0], ql4[1], ql4[2], ql4[3], sbase + AQL + wm * 144 + lofs + s * 32);
#pragma unroll
        for (int ng = 0; ng < 16; ng++) {
            LDMATRIX_X4(b4[0], b4[1], b4[2], b4[3],
                        sbase + AKH + ng * (16 * 144) + lofs + s * 32);
            MMA_F16(sacc[2 * ng], qh4, b4[0], b4[2]);
            MMA_F16(sacc[2 * ng], ql4, b4[0], b4[2]);
            MMA_F16(sacc[2 * ng + 1], qh4, b4[1], b4[3]);
            MMA_F16(sacc[2 * ng + 1], ql4, b4[1], b4[3]);
            LDMATRIX_X4(b4[0], b4[1], b4[2], b4[3],
                        sbase + AKL + ng * (16 * 144) + lofs + s * 32);
            MMA_F16(sacc[2 * ng], qh4, b4[0], b4[2]);
            MMA_F16(sacc[2 * ng + 1], qh4, b4[1], b4[3]);
        }
    }

    // --- softmax on fragments ---
    float m0 = -1e30f, m1 = -1e30f;
#pragma unroll
    for (int j = 0; j < 32; j++) {
        m0 = fmaxf(m0, fmaxf(sacc[j][0], sacc[j][1]));
        m1 = fmaxf(m1, fmaxf(sacc[j][2], sacc[j][3]));
    }
    m0 = fmaxf(m0, __shfl_xor_sync(0xffffffffu, m0, 1));
    m0 = fmaxf(m0, __shfl_xor_sync(0xffffffffu, m0, 2));
    m1 = fmaxf(m1, __shfl_xor_sync(0xffffffffu, m1, 1));
    m1 = fmaxf(m1, __shfl_xor_sync(0xffffffffu, m1, 2));

    float sum0 = 0.f, sum1 = 0.f;
#pragma unroll
    for (int j = 0; j < 32; j++) {
        float e0 = __expf((sacc[j][0] - m0) * 0.125f);
        float e1 = __expf((sacc[j][1] - m0) * 0.125f);
        float e2 = __expf((sacc[j][2] - m1) * 0.125f);
        float e3 = __expf((sacc[j][3] - m1) * 0.125f);
        sacc[j][0] = e0; sacc[j][1] = e1; sacc[j][2] = e2; sacc[j][3] = e3;
        sum0 += e0 + e1; sum1 += e2 + e3;
    }
    sum0 += __shfl_xor_sync(0xffffffffu, sum0, 1);
    sum0 += __shfl_xor_sync(0xffffffffu, sum0, 2);
    sum1 += __shfl_xor_sync(0xffffffffu, sum1, 1);
    sum1 += __shfl_xor_sync(0xffffffffu, sum1, 2);
    const float inv0 = __frcp_rn(sum0), inv1 = __frcp_rn(sum1);

    // --- ctx = P * Vp (2-term, P split in-register) ---
    float cacc[8][4];
#pragma unroll
    for (int nt = 0; nt < 8; nt++)
#pragma unroll
        for (int q = 0; q < 4; q++) cacc[nt][q] = 0.f;

#pragma unroll
    for (int s = 0; s < 16; s++) {
        uint32_t ah4[4], al4[4], b4[4];
        split2h(sacc[2 * s][0],     sacc[2 * s][1],     ah4[0], al4[0]);
        split2h(sacc[2 * s][2],     sacc[2 * s][3],     ah4[1], al4[1]);
        split2h(sacc[2 * s + 1][0], sacc[2 * s + 1][1], ah4[2], al4[2]);
        split2h(sacc[2 * s + 1][2], sacc[2 * s + 1][3], ah4[3], al4[3]);
#pragma unroll
        for (int ng = 0; ng < 4; ng++) {
            LDMATRIX_X4_T(b4[0], b4[1], b4[2], b4[3],
                          sbase + AV + s * (16 * 144) + lofs + ng * 32);
            MMA_F16(cacc[2 * ng], ah4, b4[0], b4[1]);
            MMA_F16(cacc[2 * ng], al4, b4[0], b4[1]);
            MMA_F16(cacc[2 * ng + 1], ah4, b4[2], b4[3]);
            MMA_F16(cacc[2 * ng + 1], al4, b4[2], b4[3]);
        }
    }

    const int g = lane >> 2, tig = lane & 3;
    const size_t r0 = (size_t)(b * TT + t0 + wm + g) * DD + h * 64;
    const size_t r1 = r0 + 8 * DD;
#pragma unroll
    for (int nt = 0; nt < 8; nt++) {
        const int col = nt * 8 + 2 * tig;
        uint32_t hi, lo;
        split2h(cacc[nt][0] * inv0, cacc[nt][1] * inv0, hi, lo);
        *(uint32_t*)(Ch + r0 + col) = hi;
        *(uint32_t*)(Cl + r0 + col) = lo;
        split2h(cacc[nt][2] * inv1, cacc[nt][3] * inv1, hi, lo);
        *(uint32_t*)(Ch + r1 + col) = hi;
        *(uint32_t*)(Cl + r1 + col) = lo;
    }
}

// ---------------------------------------------------------------------------
// Launch
// ---------------------------------------------------------------------------
extern "C" void kernel_launch(void* const* d_in, const int* in_sizes, int n_in,
                              void* d_out, int out_size)
{
    const float* x  = (const float*)d_in[0];
    const float* Wq = (const float*)d_in[1];
    const float* Wk = (const float*)d_in[2];
    const float* Wv = (const float*)d_in[3];
    const float* Ek = (const float*)d_in[4];
    const float* Ev = (const float*)d_in[5];
    const float* Wo = (const float*)d_in[6];
    const float* bo = (const float*)d_in[7];
    float* out = (float*)d_out;

    half_t *Ahp, *Alp, *Qhp, *Qlp, *Khp, *Klp, *Vbp, *Wtp;
    half_t *Ethp, *Etlp, *Kphp, *Kplp, *Vpp;
    cudaGetSymbolAddress((void**)&Ahp, g_Ah);
    cudaGetSymbolAddress((void**)&Alp, g_Al);
    cudaGetSymbolAddress((void**)&Qhp, g_Qh);
    cudaGetSymbolAddress((void**)&Qlp, g_Ql);
    cudaGetSymbolAddress((void**)&Khp, g_Kh);
    cudaGetSymbolAddress((void**)&Klp, g_Kl);
    cudaGetSymbolAddress((void**)&Vbp, g_V);
    cudaGetSymbolAddress((void**)&Wtp, g_Wt);
    cudaGetSymbolAddress((void**)&Ethp, g_Eth);
    cudaGetSymbolAddress((void**)&Etlp, g_Etl);
    cudaGetSymbolAddress((void**)&Kphp, g_Kph);
    cudaGetSymbolAddress((void**)&Kplp, g_Kpl);
    cudaGetSymbolAddress((void**)&Vpp, g_Vp);

    const size_t WSZ = (size_t)DD * DD;

    cudaFuncSetAttribute(tc_gemm, cudaFuncAttributeMaxDynamicSharedMemorySize, TC_SMEM);
    cudaFuncSetAttribute(proj_mma, cudaFuncAttributeMaxDynamicSharedMemorySize, PROJ_SMEM);
    cudaFuncSetAttribute(attn_mma, cudaFuncAttributeMaxDynamicSharedMemorySize, ATTN_SMEM);

    // 1) split x -> fp16 hi/lo
    split_kernel<<<2048, 256>>>(x, Ahp, Alp, MROWS * DD / 4);
    // 2) transpose+convert weights (plain) + split E
    wconv_kernel<<<dim3(DD / 32, DD / 32, 4), 256>>>(Wq, Wk, Wv, Wo, Wtp);
    esplit_kernel<<<dim3(KP / 32, TT / 32, 2), 256>>>(Ek, Ev, Ethp, Etlp);

    // 3) fused QKV projection: B = concat(WqT, WkT, WvT); Q,K split out; V plain
    tc_gemm<<<dim3(3 * DD / 128, MROWS / 128), 256, TC_SMEM>>>(
        Ahp, Alp, Wtp, nullptr, nullptr,
        Qhp, Qlp, Khp, Klp, Vbp, DD);

    // 4) low-rank projections (z=0: Kp 3-term split out; z=1: Vp 2-term plain)
    proj_mma<<<dim3(KP / 128, BHN, 2), 256, PROJ_SMEM>>>(
        Ethp, Etlp, Khp, Klp, Vbp, Kphp, Kplp, Vpp);

    // 5) fused attention -> ctx split into Ah/Al
    attn_mma<<<dim3(TT / 128, BHN), 256, ATTN_SMEM>>>(
        Qhp, Qlp, Kphp, Kplp, Vpp, Ahp, Alp);

    // 6) output projection + bias (2-term, fp32 out)
    tc_gemm<<<dim3(DD / 128, MROWS / 128), 256, TC_SMEM>>>(
        Ahp, Alp, Wtp + 3 * WSZ, out, bo,
        nullptr, nullptr, nullptr, nullptr, nullptr, DD);
}

// round 9
// speedup vs baseline: 1.5275x; 1.1877x over previous
#include <cuda_runtime.h>
#include <cuda_fp16.h>
#include <cstdint>
#include <math.h>

// Problem constants
#define BB 4
#define TT 4096
#define DD 1024
#define HH 16
#define KP 256
#define DK 64
#define MROWS (BB*TT)          // 16384
#define BHN (BB*HH)            // 64

typedef __half half_t;

// ---------------------------------------------------------------------------
// Scratch (static device globals; no allocation allowed)
// ---------------------------------------------------------------------------
__device__ half_t g_Ah[(size_t)MROWS * DD];      // x split hi (later ctx plain)
__device__ half_t g_Al[(size_t)MROWS * DD];      // x split lo
__device__ half_t g_Qh[(size_t)MROWS * DD];
__device__ half_t g_Ql[(size_t)MROWS * DD];
__device__ half_t g_Kh[(size_t)MROWS * DD];      // K split (exponent path)
__device__ half_t g_Kl[(size_t)MROWS * DD];
__device__ half_t g_V [(size_t)MROWS * DD];      // plain (linear path)
__device__ half_t g_Wt[4][(size_t)DD * DD];      // transposed [N][K], plain
__device__ half_t g_Eth[(size_t)2 * KP * TT];    // E^T split hi [z][kp][t]
__device__ half_t g_Etl[(size_t)2 * KP * TT];    // E^T split lo
__device__ half_t g_Kph[(size_t)BHN * KP * DK];  // Kp split (exponent path)
__device__ half_t g_Kpl[(size_t)BHN * KP * DK];
__device__ half_t g_Vp[(size_t)BHN * KP * DK];   // plain

// ---------------------------------------------------------------------------
// Helpers
// ---------------------------------------------------------------------------
__device__ __forceinline__ uint32_t smem_u32(const void* p) {
    uint32_t a;
    asm("{ .reg .u64 t; cvta.to.shared.u64 t, %1; cvt.u32.u64 %0, t; }" : "=r"(a) : "l"(p));
    return a;
}

#define CP_ASYNC16(dst, src) \
    asm volatile("cp.async.cg.shared.global [%0], [%1], 16;" :: "r"(dst), "l"(src))
#define CP_COMMIT() asm volatile("cp.async.commit_group;")
#define CP_WAIT1()  asm volatile("cp.async.wait_group 1;" ::: "memory")
#define CP_WAIT0()  asm volatile("cp.async.wait_group 0;" ::: "memory")

#define LDMATRIX_X4(r0, r1, r2, r3, addr) \
    asm volatile("ldmatrix.sync.aligned.m8n8.x4.shared.b16 {%0,%1,%2,%3}, [%4];" \
        : "=r"(r0), "=r"(r1), "=r"(r2), "=r"(r3) : "r"(addr))
#define LDMATRIX_X4_T(r0, r1, r2, r3, addr) \
    asm volatile("ldmatrix.sync.aligned.m8n8.x4.trans.shared.b16 {%0,%1,%2,%3}, [%4];" \
        : "=r"(r0), "=r"(r1), "=r"(r2), "=r"(r3) : "r"(addr))

#define MMA_F16(d, a, b0_, b1_) \
    asm volatile("mma.sync.aligned.m16n8k16.row.col.f32.f16.f16.f32 " \
        "{%0,%1,%2,%3},{%4,%5,%6,%7},{%8,%9},{%0,%1,%2,%3};" \
        : "+f"((d)[0]), "+f"((d)[1]), "+f"((d)[2]), "+f"((d)[3]) \
        : "r"((a)[0]), "r"((a)[1]), "r"((a)[2]), "r"((a)[3]), "r"(b0_), "r"(b1_))

__device__ __forceinline__ uint32_t pack_h2(float a, float b) {
    __half2 t = __floats2half2_rn(a, b);
    return *(uint32_t*)&t;
}
__device__ __forceinline__ void split2h(float a, float b, uint32_t& hi, uint32_t& lo) {
    __half2 h = __floats2half2_rn(a, b);
    hi = *(uint32_t*)&h;
    lo = pack_h2(a - __low2float(h), b - __high2float(h));
}

// ---------------------------------------------------------------------------
// Split fp32 -> fp16 hi/lo (vectorized x4)
// ---------------------------------------------------------------------------
__global__ __launch_bounds__(256) void split_kernel(
    const float* __restrict__ src, half_t* __restrict__ hi,
    half_t* __restrict__ lo, int n4)
{
    uint32_t* hi2 = (uint32_t*)hi;
    uint32_t* lo2 = (uint32_t*)lo;
    int stride = gridDim.x * blockDim.x;
    for (int i = blockIdx.x * blockDim.x + threadIdx.x; i < n4; i += stride) {
        float4 v = ((const float4*)src)[i];
        uint32_t h0, l0, h1, l1;
        split2h(v.x, v.y, h0, l0);
        split2h(v.z, v.w, h1, l1);
        hi2[2 * i + 0] = h0; hi2[2 * i + 1] = h1;
        lo2[2 * i + 0] = l0; lo2[2 * i + 1] = l1;
    }
}

// Transpose + convert all 4 weights (grid.z selects): [D][D] fp32 -> [N][K] fp16
__global__ __launch_bounds__(256) void wconv_kernel(
    const float* __restrict__ W0, const float* __restrict__ W1,
    const float* __restrict__ W2, const float* __restrict__ W3,
    half_t* __restrict__ WtAll)
{
    __shared__ float t[32][33];
    const int z = blockIdx.z;
    const float* W = (z == 0) ? W0 : (z == 1) ? W1 : (z == 2) ? W2 : W3;
    half_t* Wt = WtAll + (size_t)z * DD * DD;
    const int c0 = blockIdx.x * 32, r0 = blockIdx.y * 32;
    const int tx = threadIdx.x & 31, ty = threadIdx.x >> 5;
#pragma unroll
    for (int r = 0; r < 32; r += 8)
        t[ty + r][tx] = W[(size_t)(r0 + ty + r) * DD + c0 + tx];
    __syncthreads();
#pragma unroll
    for (int r = 0; r < 32; r += 8)
        Wt[(size_t)(c0 + ty + r) * DD + r0 + tx] = __float2half(t[tx][ty + r]);
}

// Transpose + split E (grid.z selects Ek/Ev): [T][KP] fp32 -> [KP][T] fp16 hi/lo
__global__ __launch_bounds__(256) void esplit_kernel(
    const float* __restrict__ E0, const float* __restrict__ E1,
    half_t* __restrict__ hiT, half_t* __restrict__ loT)
{
    __shared__ float t[32][33];
    const int z = blockIdx.z;
    const float* E = z ? E1 : E0;
    half_t* hi = hiT + (size_t)z * KP * TT;
    half_t* lo = loT + (size_t)z * KP * TT;
    const int c0 = blockIdx.x * 32, r0 = blockIdx.y * 32;
    const int tx = threadIdx.x & 31, ty = threadIdx.x >> 5;
#pragma unroll
    for (int r = 0; r < 32; r += 8)
        t[ty + r][tx] = E[(size_t)(r0 + ty + r) * KP + c0 + tx];
    __syncthreads();
#pragma unroll
    for (int r = 0; r < 32; r += 8) {
        float v = t[tx][ty + r];
        half_t h = __float2half(v);
        size_t o = (size_t)(c0 + ty + r) * TT + r0 + tx;
        hi[o] = h;
        lo[o] = __float2half(v - __half2float(h));
    }
}

// ---------------------------------------------------------------------------
// mma.sync fp16 GEMM: C = (Ah[+Al])[M,K] * B^T    (TERMS = 1 or 2)
// MODE 0: fp32 out (+bias).  MODE 1: QK routing (col<1024 -> Q split, else K
// split).  MODE 2: plain fp16 out.
// Block 128x128, K-chunk 32, 8 warps, 3-stage cp.async pipeline, 2 CTAs/SM.
// ---------------------------------------------------------------------------
#define GTILE   10240                  // 128 rows * 80 B
#define GSTAGE  (3 * GTILE)            // AH, AL, B slots (AL idle when TERMS=1)
#define TC_SMEM (3 * GSTAGE)           // 92160

template<int TERMS, int MODE>
__global__ __launch_bounds__(256, 2) void tc_gemm(
    const half_t* __restrict__ Ah, const half_t* __restrict__ Al,
    const half_t* __restrict__ Bh,
    float* __restrict__ C, const float* __restrict__ bias,
    half_t* __restrict__ O0h, half_t* __restrict__ O0l,
    half_t* __restrict__ O1h, half_t* __restrict__ O1l, int Kn)
{
    extern __shared__ char smem[];
    const uint32_t sbase = smem_u32(smem);
    const int tid = threadIdx.x, wid = tid >> 5, lane = tid & 31;
    const int warp_m = wid >> 1, warp_n = wid & 1;
    const int m0 = blockIdx.y * 128;
    const int n0g = blockIdx.x * 128;

    float acc[2][8][4];
#pragma unroll
    for (int mt = 0; mt < 2; mt++)
#pragma unroll
        for (int nt = 0; nt < 8; nt++)
#pragma unroll
            for (int q = 0; q < 4; q++) acc[mt][nt][q] = 0.f;

    const uint32_t lofs = ((((lane >> 3) & 1) * 8 + (lane & 7)) * 80u) + ((lane >> 4) * 16u);
    const int ld_row0 = tid >> 2;
    const int ld_col  = tid & 3;

    const int NC = Kn >> 5;
#define LOAD_STAGE(s, k0v) do {                                                   \
        const uint32_t stg = sbase + (uint32_t)(s) * GSTAGE;                      \
        _Pragma("unroll")                                                         \
        for (int i = 0; i < 2 * (TERMS + 1); i++) {                               \
            const int t = i >> 1;                                                 \
            const int row = (i & 1) * 64 + ld_row0;                               \
            const half_t* sp; int toff, grow;                                     \
            if (TERMS == 2) {                                                     \
                sp = (t == 0 ? Ah : t == 1 ? Al : Bh);                            \
                toff = t * GTILE;                                                 \
                grow = (t < 2 ? m0 : n0g) + row;                                  \
            } else {                                                              \
                sp = (t == 0 ? Ah : Bh);                                          \
                toff = (t == 0 ? 0 : 2 * GTILE);                                  \
                grow = (t == 0 ? m0 : n0g) + row;                                 \
            }                                                                     \
            CP_ASYNC16(stg + toff + row * 80 + ld_col * 16,                       \
                       sp + (size_t)grow * Kn + (k0v) + ld_col * 8);              \
        }                                                                         \
        CP_COMMIT();                                                              \
    } while (0)

    LOAD_STAGE(0, 0);
    LOAD_STAGE(1, 32);

    for (int c = 0; c < NC; c++) {
        const bool more = (c + 2 < NC);
        if (more) { CP_WAIT1(); } else { CP_WAIT0(); }   // tail: full drain
        __syncthreads();
        if (more) LOAD_STAGE((c + 2) % 3, (c + 2) << 5);

        const uint32_t stg = sbase + (uint32_t)(c % 3) * GSTAGE;
        const uint32_t a_base = stg + (warp_m * 32) * 80 + lofs;
        const uint32_t b_base = stg + 2 * GTILE + (warp_n * 64) * 80 + lofs;

#pragma unroll
        for (int ks = 0; ks < 2; ks++) {
            uint32_t ah[2][4], al[2][4], b[4][4];
#pragma unroll
            for (int mt = 0; mt < 2; mt++) {
                LDMATRIX_X4(ah[mt][0], ah[mt][1], ah[mt][2], ah[mt][3],
                            a_base + mt * (16 * 80) + ks * 32);
                if (TERMS == 2)
                    LDMATRIX_X4(al[mt][0], al[mt][1], al[mt][2], al[mt][3],
                                a_base + GTILE + mt * (16 * 80) + ks * 32);
            }
#pragma unroll
            for (int nq = 0; nq < 4; nq++)
                LDMATRIX_X4(b[nq][0], b[nq][1], b[nq][2], b[nq][3],
                            b_base + nq * (16 * 80) + ks * 32);
#pragma unroll
            for (int mt = 0; mt < 2; mt++)
#pragma unroll
                for (int nt = 0; nt < 8; nt++) {
                    const int nq = nt >> 1, sel = nt & 1;
                    MMA_F16(acc[mt][nt], ah[mt], b[nq][sel], b[nq][sel + 2]);
                    if (TERMS == 2)
                        MMA_F16(acc[mt][nt], al[mt], b[nq][sel], b[nq][sel + 2]);
                }
        }
    }
#undef LOAD_STAGE

    const int g = lane >> 2, tig = lane & 3;
#pragma unroll
    for (int mt = 0; mt < 2; mt++) {
        const int row0 = m0 + warp_m * 32 + mt * 16 + g;
#pragma unroll
        for (int nt = 0; nt < 8; nt++) {
            const int colg = n0g + warp_n * 64 + nt * 8 + 2 * tig;
            if (MODE == 0) {
                float bx = 0.f, by = 0.f;
                if (bias) { bx = bias[colg]; by = bias[colg + 1]; }
                *(float2*)(C + (size_t)row0 * DD + colg) =
                    make_float2(acc[mt][nt][0] + bx, acc[mt][nt][1] + by);
                *(float2*)(C + (size_t)(row0 + 8) * DD + colg) =
                    make_float2(acc[mt][nt][2] + bx, acc[mt][nt][3] + by);
            } else if (MODE == 1) {
                const int which = colg >> 10;
                const int col = colg & 1023;
                const size_t o0 = (size_t)row0 * DD + col;
                const size_t o1 = (size_t)(row0 + 8) * DD + col;
                half_t* H = (which == 0) ? O0h : O1h;
                half_t* L = (which == 0) ? O0l : O1l;
                uint32_t hi, lo;
                split2h(acc[mt][nt][0], acc[mt][nt][1], hi, lo);
                *(uint32_t*)(H + o0) = hi; *(uint32_t*)(L + o0) = lo;
                split2h(acc[mt][nt][2], acc[mt][nt][3], hi, lo);
                *(uint32_t*)(H + o1) = hi; *(uint32_t*)(L + o1) = lo;
            } else {
                const size_t o0 = (size_t)row0 * DD + colg;
                const size_t o1 = (size_t)(row0 + 8) * DD + colg;
                *(uint32_t*)(O0h + o0) = pack_h2(acc[mt][nt][0], acc[mt][nt][1]);
                *(uint32_t*)(O0h + o1) = pack_h2(acc[mt][nt][2], acc[mt][nt][3]);
            }
        }
    }
}

// ---------------------------------------------------------------------------
// Low-rank projection on MMA, 3-stage pipeline:
//   z=0: Kp = (Eh+El)^T * (Kh+Kl), 3 MMAs, split output (exponent path)
//   z=1: Vp = (Eh+El)^T * V,       2 MMAs, plain output
// grid = (KP/128, BHN, 2)
// ---------------------------------------------------------------------------
#define PAH 0
#define PALo 10240
#define PBH 20480
#define PBL (PBH + 32 * 144)
#define PSTAGE (PBL + 32 * 144)         // 29696
#define PROJ_SMEM (3 * PSTAGE)          // 89088

__global__ __launch_bounds__(256) void proj_mma(
    const half_t* __restrict__ Eh, const half_t* __restrict__ El,
    const half_t* __restrict__ Khp, const half_t* __restrict__ Klp,
    const half_t* __restrict__ Vb,
    half_t* __restrict__ Kph, half_t* __restrict__ Kpl,
    half_t* __restrict__ Vp)
{
    extern __shared__ char smem[];
    const uint32_t sbase = smem_u32(smem);
    const int tid = threadIdx.x, wid = tid >> 5, lane = tid & 31;
    const int m0k = blockIdx.x * 128;
    const int bh = blockIdx.y, z = blockIdx.z;
    const int b = bh >> 4, h = bh & 15;

    const half_t* Xh = z ? Vb : Khp;
    const half_t* Xl = Klp;            // used only when z==0
    const bool use_bl = (z == 0);
    const size_t eoff = (size_t)z * KP * TT;
    const size_t brow = (size_t)b * TT;
    const int hcol = h * 64;

    float cacc[8][4];
#pragma unroll
    for (int nt = 0; nt < 8; nt++)
#pragma unroll
        for (int q = 0; q < 4; q++) cacc[nt][q] = 0.f;

    const uint32_t lofsA = (lane & 15) * 80u + ((lane >> 4) * 16u);
    const uint32_t lofsB = (lane & 15) * 144u + ((lane >> 4) * 16u);
    const int wm = wid * 16;

#define PROJ_LOAD(s, k0v) do {                                                    \
        const uint32_t stg = sbase + (uint32_t)(s) * PSTAGE;                      \
        _Pragma("unroll")                                                         \
        for (int i = 0; i < 2; i++) {                                             \
            const int idx = tid + i * 256;                                        \
            const int r = idx >> 2, cc = idx & 3;                                 \
            const size_t gof = (size_t)(m0k + r) * TT + (k0v) + cc * 8;           \
            CP_ASYNC16(stg + PAH + r * 80 + cc * 16, Eh + eoff + gof);            \
            CP_ASYNC16(stg + PALo + r * 80 + cc * 16, El + eoff + gof);           \
        }                                                                         \
        {                                                                         \
            const int r = tid >> 3, cc = tid & 7;                                 \
            const size_t gof = (brow + (k0v) + r) * DD + hcol + cc * 8;           \
            CP_ASYNC16(stg + PBH + r * 144 + cc * 16, Xh + gof);                  \
            if (use_bl)                                                           \
                CP_ASYNC16(stg + PBL + r * 144 + cc * 16, Xl + gof);              \
        }                                                                         \
        CP_COMMIT();                                                              \
    } while (0)

    PROJ_LOAD(0, 0);
    PROJ_LOAD(1, 32);
    const int NC = TT >> 5;
    for (int c = 0; c < NC; c++) {
        const bool more = (c + 2 < NC);
        if (more) { CP_WAIT1(); } else { CP_WAIT0(); }   // tail: full drain
        __syncthreads();
        if (more) PROJ_LOAD((c + 2) % 3, (c + 2) << 5);

        const uint32_t stg = sbase + (uint32_t)(c % 3) * PSTAGE;
#pragma unroll
        for (int s = 0; s < 2; s++) {
            uint32_t ah[4], al[4], b4[4];
            LDMATRIX_X4(ah[0], ah[1], ah[2], ah[3], stg + PAH + wm * 80 + lofsA + s * 32);
            LDMATRIX_X4(al[0], al[1], al[2], al[3], stg + PALo + wm * 80 + lofsA + s * 32);
#pragma unroll
            for (int ng = 0; ng < 4; ng++) {
                LDMATRIX_X4_T(b4[0], b4[1], b4[2], b4[3],
                              stg + PBH + s * (16 * 144) + lofsB + ng * 32);
                MMA_F16(cacc[2 * ng], ah, b4[0], b4[1]);
                MMA_F16(cacc[2 * ng], al, b4[0], b4[1]);
                MMA_F16(cacc[2 * ng + 1], ah, b4[2], b4[3]);
                MMA_F16(cacc[2 * ng + 1], al, b4[2], b4[3]);
                if (use_bl) {
                    LDMATRIX_X4_T(b4[0], b4[1], b4[2], b4[3],
                                  stg + PBL + s * (16 * 144) + lofsB + ng * 32);
                    MMA_F16(cacc[2 * ng], ah, b4[0], b4[1]);
                    MMA_F16(cacc[2 * ng + 1], ah, b4[2], b4[3]);
                }
            }
        }
    }
#undef PROJ_LOAD

    const int g = lane >> 2, tig = lane & 3;
    const size_t obase = (size_t)bh * KP * DK;
#pragma unroll
    for (int nt = 0; nt < 8; nt++) {
        const int row0 = m0k + wm + g;
        const int col = nt * 8 + 2 * tig;
        const size_t o0 = obase + (size_t)row0 * DK + col;
        const size_t o1 = obase + (size_t)(row0 + 8) * DK + col;
        if (z == 0) {
            uint32_t hi, lo;
            split2h(cacc[nt][0], cacc[nt][1], hi, lo);
            *(uint32_t*)(Kph + o0) = hi; *(uint32_t*)(Kpl + o0) = lo;
            split2h(cacc[nt][2], cacc[nt][3], hi, lo);
            *(uint32_t*)(Kph + o1) = hi; *(uint32_t*)(Kpl + o1) = lo;
        } else {
            *(uint32_t*)(Vp + o0) = pack_h2(cacc[nt][0], cacc[nt][1]);
            *(uint32_t*)(Vp + o1) = pack_h2(cacc[nt][2], cacc[nt][3]);
        }
    }
}

// ---------------------------------------------------------------------------
// Fused MMA attention per (bh, 128-row t-tile):
//   S = (Qh+Ql)*(Kph+Kpl)^T   (3 MMAs — exponent path exact)
//   softmax on fragments; ctx = (Ph+Pl)*Vp (2 MMAs); ctx plain fp16 to Ch.
// ---------------------------------------------------------------------------
#define AQH 0
#define AQL (AQH + 128 * 144)
#define AKH (AQL + 128 * 144)
#define AKL (AKH + 256 * 144)
#define AV  (AKL + 256 * 144)
#define ATTN_SMEM (AV + 256 * 144)      // 147456

__global__ __launch_bounds__(256) void attn_mma(
    const half_t* __restrict__ Qh, const half_t* __restrict__ Ql,
    const half_t* __restrict__ Kp, const half_t* __restrict__ Kpl,
    const half_t* __restrict__ Vp,
    half_t* __restrict__ Ch)
{
    extern __shared__ char smem[];
    const uint32_t sbase = smem_u32(smem);
    const int tid = threadIdx.x, wid = tid >> 5, lane = tid & 31;
    const int bh = blockIdx.y, b = bh >> 4, h = bh & 15;
    const int t0 = blockIdx.x * 128;

    const size_t qbase = (size_t)(b * TT + t0) * DD + h * 64;
    for (int idx = tid; idx < 128 * 8; idx += 256) {
        const int r = idx >> 3, c = idx & 7;
        const size_t go = qbase + (size_t)r * DD + c * 8;
        *(uint4*)(smem + AQH + r * 144 + c * 16) = *(const uint4*)(Qh + go);
        *(uint4*)(smem + AQL + r * 144 + c * 16) = *(const uint4*)(Ql + go);
    }
    const size_t kpb = (size_t)bh * KP * DK;
    for (int idx = tid; idx < 256 * 8; idx += 256) {
        const int r = idx >> 3, c = idx & 7;
        const size_t go = kpb + (size_t)r * DK + c * 8;
        *(uint4*)(smem + AKH + r * 144 + c * 16) = *(const uint4*)(Kp + go);
        *(uint4*)(smem + AKL + r * 144 + c * 16) = *(const uint4*)(Kpl + go);
        *(uint4*)(smem + AV + r * 144 + c * 16) = *(const uint4*)(Vp + go);
    }
    __syncthreads();

    const int wm = wid * 16;
    const uint32_t lofs = (lane & 15) * 144u + ((lane >> 4) * 16u);

    // --- scores (3-term) ---
    float sacc[32][4];
#pragma unroll
    for (int j = 0; j < 32; j++)
#pragma unroll
        for (int q = 0; q < 4; q++) sacc[j][q] = 0.f;

#pragma unroll
    for (int s = 0; s < 4; s++) {
        uint32_t qh4[4], ql4[4], b4[4];
        LDMATRIX_X4(qh4[0], qh4[1], qh4[2], qh4[3], sbase + AQH + wm * 144 + lofs + s * 32);
        LDMATRIX_X4(ql4[0], ql4[1], ql4[2], ql4[3], sbase + AQL + wm * 144 + lofs + s * 32);
#pragma unroll
        for (int ng = 0; ng < 16; ng++) {
            LDMATRIX_X4(b4[0], b4[1], b4[2], b4[3],
                        sbase + AKH + ng * (16 * 144) + lofs + s * 32);
            MMA_F16(sacc[2 * ng], qh4, b4[0], b4[2]);
            MMA_F16(sacc[2 * ng], ql4, b4[0], b4[2]);
            MMA_F16(sacc[2 * ng + 1], qh4, b4[1], b4[3]);
            MMA_F16(sacc[2 * ng + 1], ql4, b4[1], b4[3]);
            LDMATRIX_X4(b4[0], b4[1], b4[2], b4[3],
                        sbase + AKL + ng * (16 * 144) + lofs + s * 32);
            MMA_F16(sacc[2 * ng], qh4, b4[0], b4[2]);
            MMA_F16(sacc[2 * ng + 1], qh4, b4[1], b4[3]);
        }
    }

    // --- softmax on fragments ---
    float m0 = -1e30f, m1 = -1e30f;
#pragma unroll
    for (int j = 0; j < 32; j++) {
        m0 = fmaxf(m0, fmaxf(sacc[j][0], sacc[j][1]));
        m1 = fmaxf(m1, fmaxf(sacc[j][2], sacc[j][3]));
    }
    m0 = fmaxf(m0, __shfl_xor_sync(0xffffffffu, m0, 1));
    m0 = fmaxf(m0, __shfl_xor_sync(0xffffffffu, m0, 2));
    m1 = fmaxf(m1, __shfl_xor_sync(0xffffffffu, m1, 1));
    m1 = fmaxf(m1, __shfl_xor_sync(0xffffffffu, m1, 2));

    float sum0 = 0.f, sum1 = 0.f;
#pragma unroll
    for (int j = 0; j < 32; j++) {
        float e0 = __expf((sacc[j][0] - m0) * 0.125f);
        float e1 = __expf((sacc[j][1] - m0) * 0.125f);
        float e2 = __expf((sacc[j][2] - m1) * 0.125f);
        float e3 = __expf((sacc[j][3] - m1) * 0.125f);
        sacc[j][0] = e0; sacc[j][1] = e1; sacc[j][2] = e2; sacc[j][3] = e3;
        sum0 += e0 + e1; sum1 += e2 + e3;
    }
    sum0 += __shfl_xor_sync(0xffffffffu, sum0, 1);
    sum0 += __shfl_xor_sync(0xffffffffu, sum0, 2);
    sum1 += __shfl_xor_sync(0xffffffffu, sum1, 1);
    sum1 += __shfl_xor_sync(0xffffffffu, sum1, 2);
    const float inv0 = __frcp_rn(sum0), inv1 = __frcp_rn(sum1);

    // --- ctx = P * Vp (2-term, P split in-register) ---
    float cacc[8][4];
#pragma unroll
    for (int nt = 0; nt < 8; nt++)
#pragma unroll
        for (int q = 0; q < 4; q++) cacc[nt][q] = 0.f;

#pragma unroll
    for (int s = 0; s < 16; s++) {
        uint32_t ah4[4], al4[4], b4[4];
        split2h(sacc[2 * s][0],     sacc[2 * s][1],     ah4[0], al4[0]);
        split2h(sacc[2 * s][2],     sacc[2 * s][3],     ah4[1], al4[1]);
        split2h(sacc[2 * s + 1][0], sacc[2 * s + 1][1], ah4[2], al4[2]);
        split2h(sacc[2 * s + 1][2], sacc[2 * s + 1][3], ah4[3], al4[3]);
#pragma unroll
        for (int ng = 0; ng < 4; ng++) {
            LDMATRIX_X4_T(b4[0], b4[1], b4[2], b4[3],
                          sbase + AV + s * (16 * 144) + lofs + ng * 32);
            MMA_F16(cacc[2 * ng], ah4, b4[0], b4[1]);
            MMA_F16(cacc[2 * ng], al4, b4[0], b4[1]);
            MMA_F16(cacc[2 * ng + 1], ah4, b4[2], b4[3]);
            MMA_F16(cacc[2 * ng + 1], al4, b4[2], b4[3]);
        }
    }

    // --- epilogue: normalize, write plain fp16 ctx ---
    const int g = lane >> 2, tig = lane & 3;
    const size_t r0 = (size_t)(b * TT + t0 + wm + g) * DD + h * 64;
    const size_t r1 = r0 + 8 * DD;
#pragma unroll
    for (int nt = 0; nt < 8; nt++) {
        const int col = nt * 8 + 2 * tig;
        *(uint32_t*)(Ch + r0 + col) = pack_h2(cacc[nt][0] * inv0, cacc[nt][1] * inv0);
        *(uint32_t*)(Ch + r1 + col) = pack_h2(cacc[nt][2] * inv1, cacc[nt][3] * inv1);
    }
}

// ---------------------------------------------------------------------------
// Launch
// ---------------------------------------------------------------------------
extern "C" void kernel_launch(void* const* d_in, const int* in_sizes, int n_in,
                              void* d_out, int out_size)
{
    const float* x  = (const float*)d_in[0];
    const float* Wq = (const float*)d_in[1];
    const float* Wk = (const float*)d_in[2];
    const float* Wv = (const float*)d_in[3];
    const float* Ek = (const float*)d_in[4];
    const float* Ev = (const float*)d_in[5];
    const float* Wo = (const float*)d_in[6];
    const float* bo = (const float*)d_in[7];
    float* out = (float*)d_out;

    half_t *Ahp, *Alp, *Qhp, *Qlp, *Khp, *Klp, *Vbp, *Wtp;
    half_t *Ethp, *Etlp, *Kphp, *Kplp, *Vpp;
    cudaGetSymbolAddress((void**)&Ahp, g_Ah);
    cudaGetSymbolAddress((void**)&Alp, g_Al);
    cudaGetSymbolAddress((void**)&Qhp, g_Qh);
    cudaGetSymbolAddress((void**)&Qlp, g_Ql);
    cudaGetSymbolAddress((void**)&Khp, g_Kh);
    cudaGetSymbolAddress((void**)&Klp, g_Kl);
    cudaGetSymbolAddress((void**)&Vbp, g_V);
    cudaGetSymbolAddress((void**)&Wtp, g_Wt);
    cudaGetSymbolAddress((void**)&Ethp, g_Eth);
    cudaGetSymbolAddress((void**)&Etlp, g_Etl);
    cudaGetSymbolAddress((void**)&Kphp, g_Kph);
    cudaGetSymbolAddress((void**)&Kplp, g_Kpl);
    cudaGetSymbolAddress((void**)&Vpp, g_Vp);

    const size_t WSZ = (size_t)DD * DD;

    cudaFuncSetAttribute(tc_gemm<2,1>, cudaFuncAttributeMaxDynamicSharedMemorySize, TC_SMEM);
    cudaFuncSetAttribute(tc_gemm<1,2>, cudaFuncAttributeMaxDynamicSharedMemorySize, TC_SMEM);
    cudaFuncSetAttribute(tc_gemm<1,0>, cudaFuncAttributeMaxDynamicSharedMemorySize, TC_SMEM);
    cudaFuncSetAttribute(proj_mma, cudaFuncAttributeMaxDynamicSharedMemorySize, PROJ_SMEM);
    cudaFuncSetAttribute(attn_mma, cudaFuncAttributeMaxDynamicSharedMemorySize, ATTN_SMEM);

    // 1) split x -> fp16 hi/lo
    split_kernel<<<2048, 256>>>(x, Ahp, Alp, MROWS * DD / 4);
    // 2) transpose+convert weights (plain) + split E
    wconv_kernel<<<dim3(DD / 32, DD / 32, 4), 256>>>(Wq, Wk, Wv, Wo, Wtp);
    esplit_kernel<<<dim3(KP / 32, TT / 32, 2), 256>>>(Ek, Ev, Ethp, Etlp);

    // 3a) QK projection (2-term, exponent path): B = concat(WqT, WkT)
    tc_gemm<2,1><<<dim3(2 * DD / 128, MROWS / 128), 256, TC_SMEM>>>(
        Ahp, Alp, Wtp, nullptr, nullptr, Qhp, Qlp, Khp, Klp, DD);
    // 3b) V projection (1-term, linear path): B = WvT
    tc_gemm<1,2><<<dim3(DD / 128, MROWS / 128), 256, TC_SMEM>>>(
        Ahp, nullptr, Wtp + 2 * WSZ, nullptr, nullptr, Vbp, nullptr, nullptr, nullptr, DD);

    // 4) low-rank projections (z=0: Kp 3-term split out; z=1: Vp 2-term plain)
    proj_mma<<<dim3(KP / 128, BHN, 2), 256, PROJ_SMEM>>>(
        Ethp, Etlp, Khp, Klp, Vbp, Kphp, Kplp, Vpp);

    // 5) fused attention -> ctx plain fp16 into Ah
    attn_mma<<<dim3(TT / 128, BHN), 256, ATTN_SMEM>>>(
        Qhp, Qlp, Kphp, Kplp, Vpp, Ahp);

    // 6) output projection + bias (1-term, fp32 out)
    tc_gemm<1,0><<<dim3(DD / 128, MROWS / 128), 256, TC_SMEM>>>(
        Ahp, nullptr, Wtp + 3 * WSZ, out, bo, nullptr, nullptr, nullptr, nullptr, DD);
}

// round 10
// speedup vs baseline: 1.5641x; 1.0239x over previous
#include <cuda_runtime.h>
#include <cuda_fp16.h>
#include <cstdint>
#include <math.h>

// Problem constants
#define BB 4
#define TT 4096
#define DD 1024
#define HH 16
#define KP 256
#define DK 64
#define MROWS (BB*TT)          // 16384
#define BHN (BB*HH)            // 64

typedef __half half_t;

// ---------------------------------------------------------------------------
// Scratch (static device globals; no allocation allowed)
// ---------------------------------------------------------------------------
__device__ half_t g_Ah[(size_t)MROWS * DD];      // x split hi (later ctx plain)
__device__ half_t g_Al[(size_t)MROWS * DD];      // x split lo
__device__ half_t g_Qh[(size_t)MROWS * DD];
__device__ half_t g_Ql[(size_t)MROWS * DD];
__device__ half_t g_Kh[(size_t)MROWS * DD];      // K split (exponent path)
__device__ half_t g_Kl[(size_t)MROWS * DD];
__device__ half_t g_V [(size_t)MROWS * DD];      // plain (linear path)
__device__ half_t g_Wt[4][(size_t)DD * DD];      // transposed [N][K], plain
__device__ half_t g_Eth[(size_t)2 * KP * TT];    // E^T split hi [z][kp][t]
__device__ half_t g_Etl[(size_t)2 * KP * TT];    // E^T split lo
__device__ half_t g_Kph[(size_t)BHN * KP * DK];  // Kp split (exponent path)
__device__ half_t g_Kpl[(size_t)BHN * KP * DK];
__device__ half_t g_Vp[(size_t)BHN * KP * DK];   // plain

// ---------------------------------------------------------------------------
// Helpers
// ---------------------------------------------------------------------------
__device__ __forceinline__ uint32_t smem_u32(const void* p) {
    uint32_t a;
    asm("{ .reg .u64 t; cvta.to.shared.u64 t, %1; cvt.u32.u64 %0, t; }" : "=r"(a) : "l"(p));
    return a;
}

#define CP_ASYNC16(dst, src) \
    asm volatile("cp.async.cg.shared.global [%0], [%1], 16;" :: "r"(dst), "l"(src))
#define CP_COMMIT() asm volatile("cp.async.commit_group;")
#define CP_WAIT1()  asm volatile("cp.async.wait_group 1;" ::: "memory")
#define CP_WAIT0()  asm volatile("cp.async.wait_group 0;" ::: "memory")

#define LDMATRIX_X4(r0, r1, r2, r3, addr) \
    asm volatile("ldmatrix.sync.aligned.m8n8.x4.shared.b16 {%0,%1,%2,%3}, [%4];" \
        : "=r"(r0), "=r"(r1), "=r"(r2), "=r"(r3) : "r"(addr))
#define LDMATRIX_X4_T(r0, r1, r2, r3, addr) \
    asm volatile("ldmatrix.sync.aligned.m8n8.x4.trans.shared.b16 {%0,%1,%2,%3}, [%4];" \
        : "=r"(r0), "=r"(r1), "=r"(r2), "=r"(r3) : "r"(addr))

#define MMA_F16(d, a, b0_, b1_) \
    asm volatile("mma.sync.aligned.m16n8k16.row.col.f32.f16.f16.f32 " \
        "{%0,%1,%2,%3},{%4,%5,%6,%7},{%8,%9},{%0,%1,%2,%3};" \
        : "+f"((d)[0]), "+f"((d)[1]), "+f"((d)[2]), "+f"((d)[3]) \
        : "r"((a)[0]), "r"((a)[1]), "r"((a)[2]), "r"((a)[3]), "r"(b0_), "r"(b1_))

__device__ __forceinline__ uint32_t pack_h2(float a, float b) {
    __half2 t = __floats2half2_rn(a, b);
    return *(uint32_t*)&t;
}
__device__ __forceinline__ void split2h(float a, float b, uint32_t& hi, uint32_t& lo) {
    __half2 h = __floats2half2_rn(a, b);
    hi = *(uint32_t*)&h;
    lo = pack_h2(a - __low2float(h), b - __high2float(h));
}

// ---------------------------------------------------------------------------
// Split fp32 -> fp16 hi/lo (vectorized x4)
// ---------------------------------------------------------------------------
__global__ __launch_bounds__(256) void split_kernel(
    const float* __restrict__ src, half_t* __restrict__ hi,
    half_t* __restrict__ lo, int n4)
{
    uint32_t* hi2 = (uint32_t*)hi;
    uint32_t* lo2 = (uint32_t*)lo;
    int stride = gridDim.x * blockDim.x;
    for (int i = blockIdx.x * blockDim.x + threadIdx.x; i < n4; i += stride) {
        float4 v = ((const float4*)src)[i];
        uint32_t h0, l0, h1, l1;
        split2h(v.x, v.y, h0, l0);
        split2h(v.z, v.w, h1, l1);
        hi2[2 * i + 0] = h0; hi2[2 * i + 1] = h1;
        lo2[2 * i + 0] = l0; lo2[2 * i + 1] = l1;
    }
}

// Transpose + convert all 4 weights (grid.z selects): [D][D] fp32 -> [N][K] fp16
__global__ __launch_bounds__(256) void wconv_kernel(
    const float* __restrict__ W0, const float* __restrict__ W1,
    const float* __restrict__ W2, const float* __restrict__ W3,
    half_t* __restrict__ WtAll)
{
    __shared__ float t[32][33];
    const int z = blockIdx.z;
    const float* W = (z == 0) ? W0 : (z == 1) ? W1 : (z == 2) ? W2 : W3;
    half_t* Wt = WtAll + (size_t)z * DD * DD;
    const int c0 = blockIdx.x * 32, r0 = blockIdx.y * 32;
    const int tx = threadIdx.x & 31, ty = threadIdx.x >> 5;
#pragma unroll
    for (int r = 0; r < 32; r += 8)
        t[ty + r][tx] = W[(size_t)(r0 + ty + r) * DD + c0 + tx];
    __syncthreads();
#pragma unroll
    for (int r = 0; r < 32; r += 8)
        Wt[(size_t)(c0 + ty + r) * DD + r0 + tx] = __float2half(t[tx][ty + r]);
}

// Transpose + split E (grid.z selects Ek/Ev): [T][KP] fp32 -> [KP][T] fp16 hi/lo
__global__ __launch_bounds__(256) void esplit_kernel(
    const float* __restrict__ E0, const float* __restrict__ E1,
    half_t* __restrict__ hiT, half_t* __restrict__ loT)
{
    __shared__ float t[32][33];
    const int z = blockIdx.z;
    const float* E = z ? E1 : E0;
    half_t* hi = hiT + (size_t)z * KP * TT;
    half_t* lo = loT + (size_t)z * KP * TT;
    const int c0 = blockIdx.x * 32, r0 = blockIdx.y * 32;
    const int tx = threadIdx.x & 31, ty = threadIdx.x >> 5;
#pragma unroll
    for (int r = 0; r < 32; r += 8)
        t[ty + r][tx] = E[(size_t)(r0 + ty + r) * KP + c0 + tx];
    __syncthreads();
#pragma unroll
    for (int r = 0; r < 32; r += 8) {
        float v = t[tx][ty + r];
        half_t h = __float2half(v);
        size_t o = (size_t)(c0 + ty + r) * TT + r0 + tx;
        hi[o] = h;
        lo[o] = __float2half(v - __half2float(h));
    }
}

// ---------------------------------------------------------------------------
// mma.sync fp16 GEMM: C = (Ah[+Al])[M,K] * B^T    (TERMS = 1 or 2)
// MODE 0: fp32 out (+bias).  MODE 1: QK routing (col<1024 -> Q split, else K
// split).  MODE 2: plain fp16 out.
// Hi/lo term loops hoisted: dependent-MMA distance 16 (was 1).
// ---------------------------------------------------------------------------
#define GTILE   10240                  // 128 rows * 80 B
#define GSTAGE  (3 * GTILE)            // AH, AL, B slots (AL idle when TERMS=1)
#define TC_SMEM (3 * GSTAGE)           // 92160

template<int TERMS, int MODE>
__global__ __launch_bounds__(256, 2) void tc_gemm(
    const half_t* __restrict__ Ah, const half_t* __restrict__ Al,
    const half_t* __restrict__ Bh,
    float* __restrict__ C, const float* __restrict__ bias,
    half_t* __restrict__ O0h, half_t* __restrict__ O0l,
    half_t* __restrict__ O1h, half_t* __restrict__ O1l, int Kn)
{
    extern __shared__ char smem[];
    const uint32_t sbase = smem_u32(smem);
    const int tid = threadIdx.x, wid = tid >> 5, lane = tid & 31;
    const int warp_m = wid >> 1, warp_n = wid & 1;
    const int m0 = blockIdx.y * 128;
    const int n0g = blockIdx.x * 128;

    float acc[2][8][4];
#pragma unroll
    for (int mt = 0; mt < 2; mt++)
#pragma unroll
        for (int nt = 0; nt < 8; nt++)
#pragma unroll
            for (int q = 0; q < 4; q++) acc[mt][nt][q] = 0.f;

    const uint32_t lofs = ((((lane >> 3) & 1) * 8 + (lane & 7)) * 80u) + ((lane >> 4) * 16u);
    const int ld_row0 = tid >> 2;
    const int ld_col  = tid & 3;

    const int NC = Kn >> 5;
#define LOAD_STAGE(s, k0v) do {                                                   \
        const uint32_t stg = sbase + (uint32_t)(s) * GSTAGE;                      \
        _Pragma("unroll")                                                         \
        for (int i = 0; i < 2 * (TERMS + 1); i++) {                               \
            const int t = i >> 1;                                                 \
            const int row = (i & 1) * 64 + ld_row0;                               \
            const half_t* sp; int toff, grow;                                     \
            if (TERMS == 2) {                                                     \
                sp = (t == 0 ? Ah : t == 1 ? Al : Bh);                            \
                toff = t * GTILE;                                                 \
                grow = (t < 2 ? m0 : n0g) + row;                                  \
            } else {                                                              \
                sp = (t == 0 ? Ah : Bh);                                          \
                toff = (t == 0 ? 0 : 2 * GTILE);                                  \
                grow = (t == 0 ? m0 : n0g) + row;                                 \
            }                                                                     \
            CP_ASYNC16(stg + toff + row * 80 + ld_col * 16,                       \
                       sp + (size_t)grow * Kn + (k0v) + ld_col * 8);              \
        }                                                                         \
        CP_COMMIT();                                                              \
    } while (0)

    LOAD_STAGE(0, 0);
    LOAD_STAGE(1, 32);

    for (int c = 0; c < NC; c++) {
        const bool more = (c + 2 < NC);
        if (more) { CP_WAIT1(); } else { CP_WAIT0(); }   // tail: full drain
        __syncthreads();
        if (more) LOAD_STAGE((c + 2) % 3, (c + 2) << 5);

        const uint32_t stg = sbase + (uint32_t)(c % 3) * GSTAGE;
        const uint32_t a_base = stg + (warp_m * 32) * 80 + lofs;
        const uint32_t b_base = stg + 2 * GTILE + (warp_n * 64) * 80 + lofs;

#pragma unroll
        for (int ks = 0; ks < 2; ks++) {
            uint32_t ah[2][4], al[2][4], b[4][4];
#pragma unroll
            for (int mt = 0; mt < 2; mt++) {
                LDMATRIX_X4(ah[mt][0], ah[mt][1], ah[mt][2], ah[mt][3],
                            a_base + mt * (16 * 80) + ks * 32);
                if (TERMS == 2)
                    LDMATRIX_X4(al[mt][0], al[mt][1], al[mt][2], al[mt][3],
                                a_base + GTILE + mt * (16 * 80) + ks * 32);
            }
#pragma unroll
            for (int nq = 0; nq < 4; nq++)
                LDMATRIX_X4(b[nq][0], b[nq][1], b[nq][2], b[nq][3],
                            b_base + nq * (16 * 80) + ks * 32);
            // all hi-term MMAs first (16 independent accumulators) ...
#pragma unroll
            for (int mt = 0; mt < 2; mt++)
#pragma unroll
                for (int nt = 0; nt < 8; nt++) {
                    const int nq = nt >> 1, sel = nt & 1;
                    MMA_F16(acc[mt][nt], ah[mt], b[nq][sel], b[nq][sel + 2]);
                }
            // ... then all lo-term MMAs (RAW distance 16 per accumulator)
            if (TERMS == 2) {
#pragma unroll
                for (int mt = 0; mt < 2; mt++)
#pragma unroll
                    for (int nt = 0; nt < 8; nt++) {
                        const int nq = nt >> 1, sel = nt & 1;
                        MMA_F16(acc[mt][nt], al[mt], b[nq][sel], b[nq][sel + 2]);
                    }
            }
        }
    }
#undef LOAD_STAGE

    const int g = lane >> 2, tig = lane & 3;
#pragma unroll
    for (int mt = 0; mt < 2; mt++) {
        const int row0 = m0 + warp_m * 32 + mt * 16 + g;
#pragma unroll
        for (int nt = 0; nt < 8; nt++) {
            const int colg = n0g + warp_n * 64 + nt * 8 + 2 * tig;
            if (MODE == 0) {
                float bx = 0.f, by = 0.f;
                if (bias) { bx = bias[colg]; by = bias[colg + 1]; }
                *(float2*)(C + (size_t)row0 * DD + colg) =
                    make_float2(acc[mt][nt][0] + bx, acc[mt][nt][1] + by);
                *(float2*)(C + (size_t)(row0 + 8) * DD + colg) =
                    make_float2(acc[mt][nt][2] + bx, acc[mt][nt][3] + by);
            } else if (MODE == 1) {
                const int which = colg >> 10;
                const int col = colg & 1023;
                const size_t o0 = (size_t)row0 * DD + col;
                const size_t o1 = (size_t)(row0 + 8) * DD + col;
                half_t* H = (which == 0) ? O0h : O1h;
                half_t* L = (which == 0) ? O0l : O1l;
                uint32_t hi, lo;
                split2h(acc[mt][nt][0], acc[mt][nt][1], hi, lo);
                *(uint32_t*)(H + o0) = hi; *(uint32_t*)(L + o0) = lo;
                split2h(acc[mt][nt][2], acc[mt][nt][3], hi, lo);
                *(uint32_t*)(H + o1) = hi; *(uint32_t*)(L + o1) = lo;
            } else {
                const size_t o0 = (size_t)row0 * DD + colg;
                const size_t o1 = (size_t)(row0 + 8) * DD + colg;
                *(uint32_t*)(O0h + o0) = pack_h2(acc[mt][nt][0], acc[mt][nt][1]);
                *(uint32_t*)(O0h + o1) = pack_h2(acc[mt][nt][2], acc[mt][nt][3]);
            }
        }
    }
}

// ---------------------------------------------------------------------------
// Low-rank projection on MMA, 3-stage pipeline:
//   z=0: Kp = (Eh+El)^T * (Kh+Kl), 3 MMAs, split output (exponent path)
//   z=1: Vp = (Eh+El)^T * V,       2 MMAs, plain output
// B fragments batched (4 ng) so dependent-MMA distance is 8 (was 1).
// grid = (KP/128, BHN, 2)
// ---------------------------------------------------------------------------
#define PAH 0
#define PALo 10240
#define PBH 20480
#define PBL (PBH + 32 * 144)
#define PSTAGE (PBL + 32 * 144)         // 29696
#define PROJ_SMEM (3 * PSTAGE)          // 89088

__global__ __launch_bounds__(256) void proj_mma(
    const half_t* __restrict__ Eh, const half_t* __restrict__ El,
    const half_t* __restrict__ Khp, const half_t* __restrict__ Klp,
    const half_t* __restrict__ Vb,
    half_t* __restrict__ Kph, half_t* __restrict__ Kpl,
    half_t* __restrict__ Vp)
{
    extern __shared__ char smem[];
    const uint32_t sbase = smem_u32(smem);
    const int tid = threadIdx.x, wid = tid >> 5, lane = tid & 31;
    const int m0k = blockIdx.x * 128;
    const int bh = blockIdx.y, z = blockIdx.z;
    const int b = bh >> 4, h = bh & 15;

    const half_t* Xh = z ? Vb : Khp;
    const half_t* Xl = Klp;            // used only when z==0
    const bool use_bl = (z == 0);
    const size_t eoff = (size_t)z * KP * TT;
    const size_t brow = (size_t)b * TT;
    const int hcol = h * 64;

    float cacc[8][4];
#pragma unroll
    for (int nt = 0; nt < 8; nt++)
#pragma unroll
        for (int q = 0; q < 4; q++) cacc[nt][q] = 0.f;

    const uint32_t lofsA = (lane & 15) * 80u + ((lane >> 4) * 16u);
    const uint32_t lofsB = (lane & 15) * 144u + ((lane >> 4) * 16u);
    const int wm = wid * 16;

#define PROJ_LOAD(s, k0v) do {                                                    \
        const uint32_t stg = sbase + (uint32_t)(s) * PSTAGE;                      \
        _Pragma("unroll")                                                         \
        for (int i = 0; i < 2; i++) {                                             \
            const int idx = tid + i * 256;                                        \
            const int r = idx >> 2, cc = idx & 3;                                 \
            const size_t gof = (size_t)(m0k + r) * TT + (k0v) + cc * 8;           \
            CP_ASYNC16(stg + PAH + r * 80 + cc * 16, Eh + eoff + gof);            \
            CP_ASYNC16(stg + PALo + r * 80 + cc * 16, El + eoff + gof);           \
        }                                                                         \
        {                                                                         \
            const int r = tid >> 3, cc = tid & 7;                                 \
            const size_t gof = (brow + (k0v) + r) * DD + hcol + cc * 8;           \
            CP_ASYNC16(stg + PBH + r * 144 + cc * 16, Xh + gof);                  \
            if (use_bl)                                                           \
                CP_ASYNC16(stg + PBL + r * 144 + cc * 16, Xl + gof);              \
        }                                                                         \
        CP_COMMIT();                                                              \
    } while (0)

    PROJ_LOAD(0, 0);
    PROJ_LOAD(1, 32);
    const int NC = TT >> 5;
    for (int c = 0; c < NC; c++) {
        const bool more = (c + 2 < NC);
        if (more) { CP_WAIT1(); } else { CP_WAIT0(); }   // tail: full drain
        __syncthreads();
        if (more) PROJ_LOAD((c + 2) % 3, (c + 2) << 5);

        const uint32_t stg = sbase + (uint32_t)(c % 3) * PSTAGE;
#pragma unroll
        for (int s = 0; s < 2; s++) {
            uint32_t ah[4], al[4], bb[4][4];
            LDMATRIX_X4(ah[0], ah[1], ah[2], ah[3], stg + PAH + wm * 80 + lofsA + s * 32);
            LDMATRIX_X4(al[0], al[1], al[2], al[3], stg + PALo + wm * 80 + lofsA + s * 32);
#pragma unroll
            for (int ng = 0; ng < 4; ng++)
                LDMATRIX_X4_T(bb[ng][0], bb[ng][1], bb[ng][2], bb[ng][3],
                              stg + PBH + s * (16 * 144) + lofsB + ng * 32);
            // hi-term MMAs (8 distinct accs) ...
#pragma unroll
            for (int ng = 0; ng < 4; ng++) {
                MMA_F16(cacc[2 * ng], ah, bb[ng][0], bb[ng][1]);
                MMA_F16(cacc[2 * ng + 1], ah, bb[ng][2], bb[ng][3]);
            }
            // ... lo-term MMAs (RAW distance 8)
#pragma unroll
            for (int ng = 0; ng < 4; ng++) {
                MMA_F16(cacc[2 * ng], al, bb[ng][0], bb[ng][1]);
                MMA_F16(cacc[2 * ng + 1], al, bb[ng][2], bb[ng][3]);
            }
            if (use_bl) {
#pragma unroll
                for (int ng = 0; ng < 4; ng++)
                    LDMATRIX_X4_T(bb[ng][0], bb[ng][1], bb[ng][2], bb[ng][3],
                                  stg + PBL + s * (16 * 144) + lofsB + ng * 32);
#pragma unroll
                for (int ng = 0; ng < 4; ng++) {
                    MMA_F16(cacc[2 * ng], ah, bb[ng][0], bb[ng][1]);
                    MMA_F16(cacc[2 * ng + 1], ah, bb[ng][2], bb[ng][3]);
                }
            }
        }
    }
#undef PROJ_LOAD

    const int g = lane >> 2, tig = lane & 3;
    const size_t obase = (size_t)bh * KP * DK;
#pragma unroll
    for (int nt = 0; nt < 8; nt++) {
        const int row0 = m0k + wm + g;
        const int col = nt * 8 + 2 * tig;
        const size_t o0 = obase + (size_t)row0 * DK + col;
        const size_t o1 = obase + (size_t)(row0 + 8) * DK + col;
        if (z == 0) {
            uint32_t hi, lo;
            split2h(cacc[nt][0], cacc[nt][1], hi, lo);
            *(uint32_t*)(Kph + o0) = hi; *(uint32_t*)(Kpl + o0) = lo;
            split2h(cacc[nt][2], cacc[nt][3], hi, lo);
            *(uint32_t*)(Kph + o1) = hi; *(uint32_t*)(Kpl + o1) = lo;
        } else {
            *(uint32_t*)(Vp + o0) = pack_h2(cacc[nt][0], cacc[nt][1]);
            *(uint32_t*)(Vp + o1) = pack_h2(cacc[nt][2], cacc[nt][3]);
        }
    }
}

// ---------------------------------------------------------------------------
// Fused MMA attention per (bh, 128-row t-tile):
//   S = (Qh+Ql)*(Kph+Kpl)^T   (3 MMAs — exponent path exact)
//   softmax on fragments; ctx = (Ph+Pl)*Vp (2 MMAs); ctx plain fp16 to Ch.
// B fragments batched (4 ng) for dependent-MMA distance 8.
// ---------------------------------------------------------------------------
#define AQH 0
#define AQL (AQH + 128 * 144)
#define AKH (AQL + 128 * 144)
#define AKL (AKH + 256 * 144)
#define AV  (AKL + 256 * 144)
#define ATTN_SMEM (AV + 256 * 144)      // 147456

__global__ __launch_bounds__(256) void attn_mma(
    const half_t* __restrict__ Qh, const half_t* __restrict__ Ql,
    const half_t* __restrict__ Kp, const half_t* __restrict__ Kpl,
    const half_t* __restrict__ Vp,
    half_t* __restrict__ Ch)
{
    extern __shared__ char smem[];
    const uint32_t sbase = smem_u32(smem);
    const int tid = threadIdx.x, wid = tid >> 5, lane = tid & 31;
    const int bh = blockIdx.y, b = bh >> 4, h = bh & 15;
    const int t0 = blockIdx.x * 128;

    const size_t qbase = (size_t)(b * TT + t0) * DD + h * 64;
    for (int idx = tid; idx < 128 * 8; idx += 256) {
        const int r = idx >> 3, c = idx & 7;
        const size_t go = qbase + (size_t)r * DD + c * 8;
        *(uint4*)(smem + AQH + r * 144 + c * 16) = *(const uint4*)(Qh + go);
        *(uint4*)(smem + AQL + r * 144 + c * 16) = *(const uint4*)(Ql + go);
    }
    const size_t kpb = (size_t)bh * KP * DK;
    for (int idx = tid; idx < 256 * 8; idx += 256) {
        const int r = idx >> 3, c = idx & 7;
        const size_t go = kpb + (size_t)r * DK + c * 8;
        *(uint4*)(smem + AKH + r * 144 + c * 16) = *(const uint4*)(Kp + go);
        *(uint4*)(smem + AKL + r * 144 + c * 16) = *(const uint4*)(Kpl + go);
        *(uint4*)(smem + AV + r * 144 + c * 16) = *(const uint4*)(Vp + go);
    }
    __syncthreads();

    const int wm = wid * 16;
    const uint32_t lofs = (lane & 15) * 144u + ((lane >> 4) * 16u);

    // --- scores (3-term): process ng in batches of 4 ---
    float sacc[32][4];
#pragma unroll
    for (int j = 0; j < 32; j++)
#pragma unroll
        for (int q = 0; q < 4; q++) sacc[j][q] = 0.f;

#pragma unroll
    for (int s = 0; s < 4; s++) {
        uint32_t qh4[4], ql4[4], bb[4][4];
        LDMATRIX_X4(qh4[0], qh4[1], qh4[2], qh4[3], sbase + AQH + wm * 144 + lofs + s * 32);
        LDMATRIX_X4(ql4[0], ql4[1], ql4[2], ql4[3], sbase + AQL + wm * 144 + lofs + s * 32);
#pragma unroll
        for (int g4 = 0; g4 < 4; g4++) {
#pragma unroll
            for (int j = 0; j < 4; j++)
                LDMATRIX_X4(bb[j][0], bb[j][1], bb[j][2], bb[j][3],
                            sbase + AKH + (g4 * 4 + j) * (16 * 144) + lofs + s * 32);
            // qh*kh (8 distinct accs)
#pragma unroll
            for (int j = 0; j < 4; j++) {
                const int ng = g4 * 4 + j;
                MMA_F16(sacc[2 * ng], qh4, bb[j][0], bb[j][2]);
                MMA_F16(sacc[2 * ng + 1], qh4, bb[j][1], bb[j][3]);
            }
            // ql*kh (RAW distance 8)
#pragma unroll
            for (int j = 0; j < 4; j++) {
                const int ng = g4 * 4 + j;
                MMA_F16(sacc[2 * ng], ql4, bb[j][0], bb[j][2]);
                MMA_F16(sacc[2 * ng + 1], ql4, bb[j][1], bb[j][3]);
            }
            // qh*kl
#pragma unroll
            for (int j = 0; j < 4; j++)
                LDMATRIX_X4(bb[j][0], bb[j][1], bb[j][2], bb[j][3],
                            sbase + AKL + (g4 * 4 + j) * (16 * 144) + lofs + s * 32);
#pragma unroll
            for (int j = 0; j < 4; j++) {
                const int ng = g4 * 4 + j;
                MMA_F16(sacc[2 * ng], qh4, bb[j][0], bb[j][2]);
                MMA_F16(sacc[2 * ng + 1], qh4, bb[j][1], bb[j][3]);
            }
        }
    }

    // --- softmax on fragments ---
    float m0 = -1e30f, m1 = -1e30f;
#pragma unroll
    for (int j = 0; j < 32; j++) {
        m0 = fmaxf(m0, fmaxf(sacc[j][0], sacc[j][1]));
        m1 = fmaxf(m1, fmaxf(sacc[j][2], sacc[j][3]));
    }
    m0 = fmaxf(m0, __shfl_xor_sync(0xffffffffu, m0, 1));
    m0 = fmaxf(m0, __shfl_xor_sync(0xffffffffu, m0, 2));
    m1 = fmaxf(m1, __shfl_xor_sync(0xffffffffu, m1, 1));
    m1 = fmaxf(m1, __shfl_xor_sync(0xffffffffu, m1, 2));

    float sum0 = 0.f, sum1 = 0.f;
#pragma unroll
    for (int j = 0; j < 32; j++) {
        float e0 = __expf((sacc[j][0] - m0) * 0.125f);
        float e1 = __expf((sacc[j][1] - m0) * 0.125f);
        float e2 = __expf((sacc[j][2] - m1) * 0.125f);
        float e3 = __expf((sacc[j][3] - m1) * 0.125f);
        sacc[j][0] = e0; sacc[j][1] = e1; sacc[j][2] = e2; sacc[j][3] = e3;
        sum0 += e0 + e1; sum1 += e2 + e3;
    }
    sum0 += __shfl_xor_sync(0xffffffffu, sum0, 1);
    sum0 += __shfl_xor_sync(0xffffffffu, sum0, 2);
    sum1 += __shfl_xor_sync(0xffffffffu, sum1, 1);
    sum1 += __shfl_xor_sync(0xffffffffu, sum1, 2);
    const float inv0 = __frcp_rn(sum0), inv1 = __frcp_rn(sum1);

    // --- ctx = P * Vp (2-term, P split in-register) ---
    float cacc[8][4];
#pragma unroll
    for (int nt = 0; nt < 8; nt++)
#pragma unroll
        for (int q = 0; q < 4; q++) cacc[nt][q] = 0.f;

#pragma unroll
    for (int s = 0; s < 16; s++) {
        uint32_t ah4[4], al4[4], bb[4][4];
        split2h(sacc[2 * s][0],     sacc[2 * s][1],     ah4[0], al4[0]);
        split2h(sacc[2 * s][2],     sacc[2 * s][3],     ah4[1], al4[1]);
        split2h(sacc[2 * s + 1][0], sacc[2 * s + 1][1], ah4[2], al4[2]);
        split2h(sacc[2 * s + 1][2], sacc[2 * s + 1][3], ah4[3], al4[3]);
#pragma unroll
        for (int ng = 0; ng < 4; ng++)
            LDMATRIX_X4_T(bb[ng][0], bb[ng][1], bb[ng][2], bb[ng][3],
                          sbase + AV + s * (16 * 144) + lofs + ng * 32);
        // hi-term MMAs (8 distinct accs) ...
#pragma unroll
        for (int ng = 0; ng < 4; ng++) {
            MMA_F16(cacc[2 * ng], ah4, bb[ng][0], bb[ng][1]);
            MMA_F16(cacc[2 * ng + 1], ah4, bb[ng][2], bb[ng][3]);
        }
        // ... lo-term MMAs (RAW distance 8)
#pragma unroll
        for (int ng = 0; ng < 4; ng++) {
            MMA_F16(cacc[2 * ng], al4, bb[ng][0], bb[ng][1]);
            MMA_F16(cacc[2 * ng + 1], al4, bb[ng][2], bb[ng][3]);
        }
    }

    // --- epilogue: normalize, write plain fp16 ctx ---
    const int g = lane >> 2, tig = lane & 3;
    const size_t r0 = (size_t)(b * TT + t0 + wm + g) * DD + h * 64;
    const size_t r1 = r0 + 8 * DD;
#pragma unroll
    for (int nt = 0; nt < 8; nt++) {
        const int col = nt * 8 + 2 * tig;
        *(uint32_t*)(Ch + r0 + col) = pack_h2(cacc[nt][0] * inv0, cacc[nt][1] * inv0);
        *(uint32_t*)(Ch + r1 + col) = pack_h2(cacc[nt][2] * inv1, cacc[nt][3] * inv1);
    }
}

// ---------------------------------------------------------------------------
// Launch
// ---------------------------------------------------------------------------
extern "C" void kernel_launch(void* const* d_in, const int* in_sizes, int n_in,
                              void* d_out, int out_size)
{
    const float* x  = (const float*)d_in[0];
    const float* Wq = (const float*)d_in[1];
    const float* Wk = (const float*)d_in[2];
    const float* Wv = (const float*)d_in[3];
    const float* Ek = (const float*)d_in[4];
    const float* Ev = (const float*)d_in[5];
    const float* Wo = (const float*)d_in[6];
    const float* bo = (const float*)d_in[7];
    float* out = (float*)d_out;

    half_t *Ahp, *Alp, *Qhp, *Qlp, *Khp, *Klp, *Vbp, *Wtp;
    half_t *Ethp, *Etlp, *Kphp, *Kplp, *Vpp;
    cudaGetSymbolAddress((void**)&Ahp, g_Ah);
    cudaGetSymbolAddress((void**)&Alp, g_Al);
    cudaGetSymbolAddress((void**)&Qhp, g_Qh);
    cudaGetSymbolAddress((void**)&Qlp, g_Ql);
    cudaGetSymbolAddress((void**)&Khp, g_Kh);
    cudaGetSymbolAddress((void**)&Klp, g_Kl);
    cudaGetSymbolAddress((void**)&Vbp, g_V);
    cudaGetSymbolAddress((void**)&Wtp, g_Wt);
    cudaGetSymbolAddress((void**)&Ethp, g_Eth);
    cudaGetSymbolAddress((void**)&Etlp, g_Etl);
    cudaGetSymbolAddress((void**)&Kphp, g_Kph);
    cudaGetSymbolAddress((void**)&Kplp, g_Kpl);
    cudaGetSymbolAddress((void**)&Vpp, g_Vp);

    const size_t WSZ = (size_t)DD * DD;

    cudaFuncSetAttribute(tc_gemm<2,1>, cudaFuncAttributeMaxDynamicSharedMemorySize, TC_SMEM);
    cudaFuncSetAttribute(tc_gemm<1,2>, cudaFuncAttributeMaxDynamicSharedMemorySize, TC_SMEM);
    cudaFuncSetAttribute(tc_gemm<1,0>, cudaFuncAttributeMaxDynamicSharedMemorySize, TC_SMEM);
    cudaFuncSetAttribute(proj_mma, cudaFuncAttributeMaxDynamicSharedMemorySize, PROJ_SMEM);
    cudaFuncSetAttribute(attn_mma, cudaFuncAttributeMaxDynamicSharedMemorySize, ATTN_SMEM);

    // 1) split x -> fp16 hi/lo
    split_kernel<<<2048, 256>>>(x, Ahp, Alp, MROWS * DD / 4);
    // 2) transpose+convert weights (plain) + split E
    wconv_kernel<<<dim3(DD / 32, DD / 32, 4), 256>>>(Wq, Wk, Wv, Wo, Wtp);
    esplit_kernel<<<dim3(KP / 32, TT / 32, 2), 256>>>(Ek, Ev, Ethp, Etlp);

    // 3a) QK projection (2-term, exponent path): B = concat(WqT, WkT)
    tc_gemm<2,1><<<dim3(2 * DD / 128, MROWS / 128), 256, TC_SMEM>>>(
        Ahp, Alp, Wtp, nullptr, nullptr, Qhp, Qlp, Khp, Klp, DD);
    // 3b) V projection (1-term, linear path): B = WvT
    tc_gemm<1,2><<<dim3(DD / 128, MROWS / 128), 256, TC_SMEM>>>(
        Ahp, nullptr, Wtp + 2 * WSZ, nullptr, nullptr, Vbp, nullptr, nullptr, nullptr, DD);

    // 4) low-rank projections (z=0: Kp 3-term split out; z=1: Vp 2-term plain)
    proj_mma<<<dim3(KP / 128, BHN, 2), 256, PROJ_SMEM>>>(
        Ethp, Etlp, Khp, Klp, Vbp, Kphp, Kplp, Vpp);

    // 5) fused attention -> ctx plain fp16 into Ah
    attn_mma<<<dim3(TT / 128, BHN), 256, ATTN_SMEM>>>(
        Qhp, Qlp, Kphp, Kplp, Vpp, Ahp);

    // 6) output projection + bias (1-term, fp32 out)
    tc_gemm<1,0><<<dim3(DD / 128, MROWS / 128), 256, TC_SMEM>>>(
        Ahp, nullptr, Wtp + 3 * WSZ, out, bo, nullptr, nullptr, nullptr, nullptr, DD);
}

// round 11
// speedup vs baseline: 1.9990x; 1.2781x over previous
#include <cuda_runtime.h>
#include <cuda_fp16.h>
#include <cstdint>
#include <math.h>

// Problem constants
#define BB 4
#define TT 4096
#define DD 1024
#define HH 16
#define KP 256
#define DK 64
#define MROWS (BB*TT)          // 16384
#define BHN (BB*HH)            // 64

typedef __half half_t;

// ---------------------------------------------------------------------------
// Scratch (static device globals; no allocation allowed)
// ---------------------------------------------------------------------------
__device__ half_t g_A [(size_t)MROWS * DD];      // x plain fp16 (later ctx plain)
__device__ half_t g_Qh[(size_t)MROWS * DD];
__device__ half_t g_Ql[(size_t)MROWS * DD];
__device__ half_t g_Kh[(size_t)MROWS * DD];      // K split (exponent path)
__device__ half_t g_Kl[(size_t)MROWS * DD];
__device__ half_t g_V [(size_t)MROWS * DD];      // plain (linear path)
__device__ half_t g_Wt[4][(size_t)DD * DD];      // transposed [N][K], plain
__device__ half_t g_Eth[(size_t)2 * KP * TT];    // E^T split hi [z][kp][t]
__device__ half_t g_Etl[(size_t)2 * KP * TT];    // E^T split lo
__device__ half_t g_Kph[(size_t)BHN * KP * DK];  // Kp split (exponent path)
__device__ half_t g_Kpl[(size_t)BHN * KP * DK];
__device__ half_t g_Vp[(size_t)BHN * KP * DK];   // plain

// ---------------------------------------------------------------------------
// Helpers
// ---------------------------------------------------------------------------
__device__ __forceinline__ uint32_t smem_u32(const void* p) {
    uint32_t a;
    asm("{ .reg .u64 t; cvta.to.shared.u64 t, %1; cvt.u32.u64 %0, t; }" : "=r"(a) : "l"(p));
    return a;
}

#define CP_ASYNC16(dst, src) \
    asm volatile("cp.async.cg.shared.global [%0], [%1], 16;" :: "r"(dst), "l"(src))
#define CP_COMMIT() asm volatile("cp.async.commit_group;")
#define CP_WAIT1()  asm volatile("cp.async.wait_group 1;" ::: "memory")
#define CP_WAIT0()  asm volatile("cp.async.wait_group 0;" ::: "memory")

#define LDMATRIX_X4(r0, r1, r2, r3, addr) \
    asm volatile("ldmatrix.sync.aligned.m8n8.x4.shared.b16 {%0,%1,%2,%3}, [%4];" \
        : "=r"(r0), "=r"(r1), "=r"(r2), "=r"(r3) : "r"(addr))
#define LDMATRIX_X4_T(r0, r1, r2, r3, addr) \
    asm volatile("ldmatrix.sync.aligned.m8n8.x4.trans.shared.b16 {%0,%1,%2,%3}, [%4];" \
        : "=r"(r0), "=r"(r1), "=r"(r2), "=r"(r3) : "r"(addr))

#define MMA_F16(d, a, b0_, b1_) \
    asm volatile("mma.sync.aligned.m16n8k16.row.col.f32.f16.f16.f32 " \
        "{%0,%1,%2,%3},{%4,%5,%6,%7},{%8,%9},{%0,%1,%2,%3};" \
        : "+f"((d)[0]), "+f"((d)[1]), "+f"((d)[2]), "+f"((d)[3]) \
        : "r"((a)[0]), "r"((a)[1]), "r"((a)[2]), "r"((a)[3]), "r"(b0_), "r"(b1_))

__device__ __forceinline__ uint32_t pack_h2(float a, float b) {
    __half2 t = __floats2half2_rn(a, b);
    return *(uint32_t*)&t;
}
__device__ __forceinline__ void split2h(float a, float b, uint32_t& hi, uint32_t& lo) {
    __half2 h = __floats2half2_rn(a, b);
    hi = *(uint32_t*)&h;
    lo = pack_h2(a - __low2float(h), b - __high2float(h));
}

// ---------------------------------------------------------------------------
// Convert fp32 -> fp16 plain (vectorized x4)
// ---------------------------------------------------------------------------
__global__ __launch_bounds__(256) void conv_kernel(
    const float* __restrict__ src, half_t* __restrict__ dst, int n4)
{
    uint32_t* d2 = (uint32_t*)dst;
    int stride = gridDim.x * blockDim.x;
    for (int i = blockIdx.x * blockDim.x + threadIdx.x; i < n4; i += stride) {
        float4 v = ((const float4*)src)[i];
        d2[2 * i + 0] = pack_h2(v.x, v.y);
        d2[2 * i + 1] = pack_h2(v.z, v.w);
    }
}

// Transpose + convert all 4 weights (grid.z selects): [D][D] fp32 -> [N][K] fp16
__global__ __launch_bounds__(256) void wconv_kernel(
    const float* __restrict__ W0, const float* __restrict__ W1,
    const float* __restrict__ W2, const float* __restrict__ W3,
    half_t* __restrict__ WtAll)
{
    __shared__ float t[32][33];
    const int z = blockIdx.z;
    const float* W = (z == 0) ? W0 : (z == 1) ? W1 : (z == 2) ? W2 : W3;
    half_t* Wt = WtAll + (size_t)z * DD * DD;
    const int c0 = blockIdx.x * 32, r0 = blockIdx.y * 32;
    const int tx = threadIdx.x & 31, ty = threadIdx.x >> 5;
#pragma unroll
    for (int r = 0; r < 32; r += 8)
        t[ty + r][tx] = W[(size_t)(r0 + ty + r) * DD + c0 + tx];
    __syncthreads();
#pragma unroll
    for (int r = 0; r < 32; r += 8)
        Wt[(size_t)(c0 + ty + r) * DD + r0 + tx] = __float2half(t[tx][ty + r]);
}

// Transpose + split E (grid.z selects Ek/Ev): [T][KP] fp32 -> [KP][T] fp16 hi/lo
__global__ __launch_bounds__(256) void esplit_kernel(
    const float* __restrict__ E0, const float* __restrict__ E1,
    half_t* __restrict__ hiT, half_t* __restrict__ loT)
{
    __shared__ float t[32][33];
    const int z = blockIdx.z;
    const float* E = z ? E1 : E0;
    half_t* hi = hiT + (size_t)z * KP * TT;
    half_t* lo = loT + (size_t)z * KP * TT;
    const int c0 = blockIdx.x * 32, r0 = blockIdx.y * 32;
    const int tx = threadIdx.x & 31, ty = threadIdx.x >> 5;
#pragma unroll
    for (int r = 0; r < 32; r += 8)
        t[ty + r][tx] = E[(size_t)(r0 + ty + r) * KP + c0 + tx];
    __syncthreads();
#pragma unroll
    for (int r = 0; r < 32; r += 8) {
        float v = t[tx][ty + r];
        half_t h = __float2half(v);
        size_t o = (size_t)(c0 + ty + r) * TT + r0 + tx;
        hi[o] = h;
        lo[o] = __float2half(v - __half2float(h));
    }
}

// ---------------------------------------------------------------------------
// mma.sync fp16 GEMM: C = A[M,K] * B^T   (1-term A)
// MODE 0: fp32 out (+bias).
// MODE 1: QKV routing — col block 0 -> Q split, 1 -> K split, 2 -> V plain.
// Block 128x128, K-chunk 32, 8 warps, 3-stage cp.async pipeline, 2 CTAs/SM.
// ---------------------------------------------------------------------------
#define GTILE   10240                  // 128 rows * 80 B
#define GSTAGE  (2 * GTILE)            // A, B
#define TC_SMEM (3 * GSTAGE)           // 61440

template<int MODE>
__global__ __launch_bounds__(256, 2) void tc_gemm(
    const half_t* __restrict__ Ah, const half_t* __restrict__ Bh,
    float* __restrict__ C, const float* __restrict__ bias,
    half_t* __restrict__ Qh, half_t* __restrict__ Ql,
    half_t* __restrict__ Kho, half_t* __restrict__ Klo,
    half_t* __restrict__ Vo, int Kn)
{
    extern __shared__ char smem[];
    const uint32_t sbase = smem_u32(smem);
    const int tid = threadIdx.x, wid = tid >> 5, lane = tid & 31;
    const int warp_m = wid >> 1, warp_n = wid & 1;
    const int m0 = blockIdx.y * 128;
    const int n0g = blockIdx.x * 128;

    float acc[2][8][4];
#pragma unroll
    for (int mt = 0; mt < 2; mt++)
#pragma unroll
        for (int nt = 0; nt < 8; nt++)
#pragma unroll
            for (int q = 0; q < 4; q++) acc[mt][nt][q] = 0.f;

    const uint32_t lofs = ((((lane >> 3) & 1) * 8 + (lane & 7)) * 80u) + ((lane >> 4) * 16u);
    const int ld_row0 = tid >> 2;
    const int ld_col  = tid & 3;

    const int NC = Kn >> 5;
#define LOAD_STAGE(s, k0v) do {                                                   \
        const uint32_t stg = sbase + (uint32_t)(s) * GSTAGE;                      \
        _Pragma("unroll")                                                         \
        for (int i = 0; i < 4; i++) {                                             \
            const int t = i >> 1;                                                 \
            const int row = (i & 1) * 64 + ld_row0;                               \
            const half_t* sp = (t == 0 ? Ah : Bh);                                \
            const int grow = (t == 0 ? m0 : n0g) + row;                           \
            CP_ASYNC16(stg + t * GTILE + row * 80 + ld_col * 16,                  \
                       sp + (size_t)grow * Kn + (k0v) + ld_col * 8);              \
        }                                                                         \
        CP_COMMIT();                                                              \
    } while (0)

    LOAD_STAGE(0, 0);
    LOAD_STAGE(1, 32);

    for (int c = 0; c < NC; c++) {
        const bool more = (c + 2 < NC);
        if (more) { CP_WAIT1(); } else { CP_WAIT0(); }   // tail: full drain
        __syncthreads();
        if (more) LOAD_STAGE((c + 2) % 3, (c + 2) << 5);

        const uint32_t stg = sbase + (uint32_t)(c % 3) * GSTAGE;
        const uint32_t a_base = stg + (warp_m * 32) * 80 + lofs;
        const uint32_t b_base = stg + GTILE + (warp_n * 64) * 80 + lofs;

#pragma unroll
        for (int ks = 0; ks < 2; ks++) {
            uint32_t ah[2][4], b[4][4];
#pragma unroll
            for (int mt = 0; mt < 2; mt++)
                LDMATRIX_X4(ah[mt][0], ah[mt][1], ah[mt][2], ah[mt][3],
                            a_base + mt * (16 * 80) + ks * 32);
#pragma unroll
            for (int nq = 0; nq < 4; nq++)
                LDMATRIX_X4(b[nq][0], b[nq][1], b[nq][2], b[nq][3],
                            b_base + nq * (16 * 80) + ks * 32);
#pragma unroll
            for (int mt = 0; mt < 2; mt++)
#pragma unroll
                for (int nt = 0; nt < 8; nt++) {
                    const int nq = nt >> 1, sel = nt & 1;
                    MMA_F16(acc[mt][nt], ah[mt], b[nq][sel], b[nq][sel + 2]);
                }
        }
    }
#undef LOAD_STAGE

    const int g = lane >> 2, tig = lane & 3;
#pragma unroll
    for (int mt = 0; mt < 2; mt++) {
        const int row0 = m0 + warp_m * 32 + mt * 16 + g;
#pragma unroll
        for (int nt = 0; nt < 8; nt++) {
            const int colg = n0g + warp_n * 64 + nt * 8 + 2 * tig;
            if (MODE == 0) {
                float bx = 0.f, by = 0.f;
                if (bias) { bx = bias[colg]; by = bias[colg + 1]; }
                *(float2*)(C + (size_t)row0 * DD + colg) =
                    make_float2(acc[mt][nt][0] + bx, acc[mt][nt][1] + by);
                *(float2*)(C + (size_t)(row0 + 8) * DD + colg) =
                    make_float2(acc[mt][nt][2] + bx, acc[mt][nt][3] + by);
            } else {
                const int which = colg >> 10;
                const int col = colg & 1023;
                const size_t o0 = (size_t)row0 * DD + col;
                const size_t o1 = (size_t)(row0 + 8) * DD + col;
                if (which == 2) {
                    *(uint32_t*)(Vo + o0) = pack_h2(acc[mt][nt][0], acc[mt][nt][1]);
                    *(uint32_t*)(Vo + o1) = pack_h2(acc[mt][nt][2], acc[mt][nt][3]);
                } else {
                    half_t* H = (which == 0) ? Qh : Kho;
                    half_t* L = (which == 0) ? Ql : Klo;
                    uint32_t hi, lo;
                    split2h(acc[mt][nt][0], acc[mt][nt][1], hi, lo);
                    *(uint32_t*)(H + o0) = hi; *(uint32_t*)(L + o0) = lo;
                    split2h(acc[mt][nt][2], acc[mt][nt][3], hi, lo);
                    *(uint32_t*)(H + o1) = hi; *(uint32_t*)(L + o1) = lo;
                }
            }
        }
    }
}

// ---------------------------------------------------------------------------
// Low-rank projection on MMA, 3-stage pipeline:
//   z=0: Kp = (Eh+El)^T * (Kh+Kl), 3 MMAs, split output (exponent path)
//   z=1: Vp = (Eh+El)^T * V,       2 MMAs, plain output
// grid = (KP/128, BHN, 2)
// ---------------------------------------------------------------------------
#define PAH 0
#define PALo 10240
#define PBH 20480
#define PBL (PBH + 32 * 144)
#define PSTAGE (PBL + 32 * 144)         // 29696
#define PROJ_SMEM (3 * PSTAGE)          // 89088

__global__ __launch_bounds__(256) void proj_mma(
    const half_t* __restrict__ Eh, const half_t* __restrict__ El,
    const half_t* __restrict__ Khp, const half_t* __restrict__ Klp,
    const half_t* __restrict__ Vb,
    half_t* __restrict__ Kph, half_t* __restrict__ Kpl,
    half_t* __restrict__ Vp)
{
    extern __shared__ char smem[];
    const uint32_t sbase = smem_u32(smem);
    const int tid = threadIdx.x, wid = tid >> 5, lane = tid & 31;
    const int m0k = blockIdx.x * 128;
    const int bh = blockIdx.y, z = blockIdx.z;
    const int b = bh >> 4, h = bh & 15;

    const half_t* Xh = z ? Vb : Khp;
    const half_t* Xl = Klp;            // used only when z==0
    const bool use_bl = (z == 0);
    const size_t eoff = (size_t)z * KP * TT;
    const size_t brow = (size_t)b * TT;
    const int hcol = h * 64;

    float cacc[8][4];
#pragma unroll
    for (int nt = 0; nt < 8; nt++)
#pragma unroll
        for (int q = 0; q < 4; q++) cacc[nt][q] = 0.f;

    const uint32_t lofsA = (lane & 15) * 80u + ((lane >> 4) * 16u);
    const uint32_t lofsB = (lane & 15) * 144u + ((lane >> 4) * 16u);
    const int wm = wid * 16;

#define PROJ_LOAD(s, k0v) do {                                                    \
        const uint32_t stg = sbase + (uint32_t)(s) * PSTAGE;                      \
        _Pragma("unroll")                                                         \
        for (int i = 0; i < 2; i++) {                                             \
            const int idx = tid + i * 256;                                        \
            const int r = idx >> 2, cc = idx & 3;                                 \
            const size_t gof = (size_t)(m0k + r) * TT + (k0v) + cc * 8;           \
            CP_ASYNC16(stg + PAH + r * 80 + cc * 16, Eh + eoff + gof);            \
            CP_ASYNC16(stg + PALo + r * 80 + cc * 16, El + eoff + gof);           \
        }                                                                         \
        {                                                                         \
            const int r = tid >> 3, cc = tid & 7;                                 \
            const size_t gof = (brow + (k0v) + r) * DD + hcol + cc * 8;           \
            CP_ASYNC16(stg + PBH + r * 144 + cc * 16, Xh + gof);                  \
            if (use_bl)                                                           \
                CP_ASYNC16(stg + PBL + r * 144 + cc * 16, Xl + gof);              \
        }                                                                         \
        CP_COMMIT();                                                              \
    } while (0)

    PROJ_LOAD(0, 0);
    PROJ_LOAD(1, 32);
    const int NC = TT >> 5;
    for (int c = 0; c < NC; c++) {
        const bool more = (c + 2 < NC);
        if (more) { CP_WAIT1(); } else { CP_WAIT0(); }   // tail: full drain
        __syncthreads();
        if (more) PROJ_LOAD((c + 2) % 3, (c + 2) << 5);

        const uint32_t stg = sbase + (uint32_t)(c % 3) * PSTAGE;
#pragma unroll
        for (int s = 0; s < 2; s++) {
            uint32_t ah[4], al[4], bb[4][4];
            LDMATRIX_X4(ah[0], ah[1], ah[2], ah[3], stg + PAH + wm * 80 + lofsA + s * 32);
            LDMATRIX_X4(al[0], al[1], al[2], al[3], stg + PALo + wm * 80 + lofsA + s * 32);
#pragma unroll
            for (int ng = 0; ng < 4; ng++)
                LDMATRIX_X4_T(bb[ng][0], bb[ng][1], bb[ng][2], bb[ng][3],
                              stg + PBH + s * (16 * 144) + lofsB + ng * 32);
#pragma unroll
            for (int ng = 0; ng < 4; ng++) {
                MMA_F16(cacc[2 * ng], ah, bb[ng][0], bb[ng][1]);
                MMA_F16(cacc[2 * ng + 1], ah, bb[ng][2], bb[ng][3]);
            }
#pragma unroll
            for (int ng = 0; ng < 4; ng++) {
                MMA_F16(cacc[2 * ng], al, bb[ng][0], bb[ng][1]);
                MMA_F16(cacc[2 * ng + 1], al, bb[ng][2], bb[ng][3]);
            }
            if (use_bl) {
#pragma unroll
                for (int ng = 0; ng < 4; ng++)
                    LDMATRIX_X4_T(bb[ng][0], bb[ng][1], bb[ng][2], bb[ng][3],
                                  stg + PBL + s * (16 * 144) + lofsB + ng * 32);
#pragma unroll
                for (int ng = 0; ng < 4; ng++) {
                    MMA_F16(cacc[2 * ng], ah, bb[ng][0], bb[ng][1]);
                    MMA_F16(cacc[2 * ng + 1], ah, bb[ng][2], bb[ng][3]);
                }
            }
        }
    }
#undef PROJ_LOAD

    const int g = lane >> 2, tig = lane & 3;
    const size_t obase = (size_t)bh * KP * DK;
#pragma unroll
    for (int nt = 0; nt < 8; nt++) {
        const int row0 = m0k + wm + g;
        const int col = nt * 8 + 2 * tig;
        const size_t o0 = obase + (size_t)row0 * DK + col;
        const size_t o1 = obase + (size_t)(row0 + 8) * DK + col;
        if (z == 0) {
            uint32_t hi, lo;
            split2h(cacc[nt][0], cacc[nt][1], hi, lo);
            *(uint32_t*)(Kph + o0) = hi; *(uint32_t*)(Kpl + o0) = lo;
            split2h(cacc[nt][2], cacc[nt][3], hi, lo);
            *(uint32_t*)(Kph + o1) = hi; *(uint32_t*)(Kpl + o1) = lo;
        } else {
            *(uint32_t*)(Vp + o0) = pack_h2(cacc[nt][0], cacc[nt][1]);
            *(uint32_t*)(Vp + o1) = pack_h2(cacc[nt][2], cacc[nt][3]);
        }
    }
}

// ---------------------------------------------------------------------------
// Fused MMA attention per (bh, 128-row t-tile):
//   S = (Qh+Ql)*(Kph+Kpl)^T   (3 MMAs — exponent path exact)
//   softmax on fragments; ctx = P*Vp (1-term, P plain fp16); ctx plain to Ch.
// ---------------------------------------------------------------------------
#define AQH 0
#define AQL (AQH + 128 * 144)
#define AKH (AQL + 128 * 144)
#define AKL (AKH + 256 * 144)
#define AV  (AKL + 256 * 144)
#define ATTN_SMEM (AV + 256 * 144)      // 147456

__global__ __launch_bounds__(256) void attn_mma(
    const half_t* __restrict__ Qh, const half_t* __restrict__ Ql,
    const half_t* __restrict__ Kp, const half_t* __restrict__ Kpl,
    const half_t* __restrict__ Vp,
    half_t* __restrict__ Ch)
{
    extern __shared__ char smem[];
    const uint32_t sbase = smem_u32(smem);
    const int tid = threadIdx.x, wid = tid >> 5, lane = tid & 31;
    const int bh = blockIdx.y, b = bh >> 4, h = bh & 15;
    const int t0 = blockIdx.x * 128;

    const size_t qbase = (size_t)(b * TT + t0) * DD + h * 64;
    for (int idx = tid; idx < 128 * 8; idx += 256) {
        const int r = idx >> 3, c = idx & 7;
        const size_t go = qbase + (size_t)r * DD + c * 8;
        *(uint4*)(smem + AQH + r * 144 + c * 16) = *(const uint4*)(Qh + go);
        *(uint4*)(smem + AQL + r * 144 + c * 16) = *(const uint4*)(Ql + go);
    }
    const size_t kpb = (size_t)bh * KP * DK;
    for (int idx = tid; idx < 256 * 8; idx += 256) {
        const int r = idx >> 3, c = idx & 7;
        const size_t go = kpb + (size_t)r * DK + c * 8;
        *(uint4*)(smem + AKH + r * 144 + c * 16) = *(const uint4*)(Kp + go);
        *(uint4*)(smem + AKL + r * 144 + c * 16) = *(const uint4*)(Kpl + go);
        *(uint4*)(smem + AV + r * 144 + c * 16) = *(const uint4*)(Vp + go);
    }
    __syncthreads();

    const int wm = wid * 16;
    const uint32_t lofs = (lane & 15) * 144u + ((lane >> 4) * 16u);

    // --- scores (3-term): process ng in batches of 4 ---
    float sacc[32][4];
#pragma unroll
    for (int j = 0; j < 32; j++)
#pragma unroll
        for (int q = 0; q < 4; q++) sacc[j][q] = 0.f;

#pragma unroll
    for (int s = 0; s < 4; s++) {
        uint32_t qh4[4], ql4[4], bb[4][4];
        LDMATRIX_X4(qh4[0], qh4[1], qh4[2], qh4[3], sbase + AQH + wm * 144 + lofs + s * 32);
        LDMATRIX_X4(ql4[0], ql4[1], ql4[2], ql4[3], sbase + AQL + wm * 144 + lofs + s * 32);
#pragma unroll
        for (int g4 = 0; g4 < 4; g4++) {
#pragma unroll
            for (int j = 0; j < 4; j++)
                LDMATRIX_X4(bb[j][0], bb[j][1], bb[j][2], bb[j][3],
                            sbase + AKH + (g4 * 4 + j) * (16 * 144) + lofs + s * 32);
#pragma unroll
            for (int j = 0; j < 4; j++) {
                const int ng = g4 * 4 + j;
                MMA_F16(sacc[2 * ng], qh4, bb[j][0], bb[j][2]);
                MMA_F16(sacc[2 * ng + 1], qh4, bb[j][1], bb[j][3]);
            }
#pragma unroll
            for (int j = 0; j < 4; j++) {
                const int ng = g4 * 4 + j;
                MMA_F16(sacc[2 * ng], ql4, bb[j][0], bb[j][2]);
                MMA_F16(sacc[2 * ng + 1], ql4, bb[j][1], bb[j][3]);
            }
#pragma unroll
            for (int j = 0; j < 4; j++)
                LDMATRIX_X4(bb[j][0], bb[j][1], bb[j][2], bb[j][3],
                            sbase + AKL + (g4 * 4 + j) * (16 * 144) + lofs + s * 32);
#pragma unroll
            for (int j = 0; j < 4; j++) {
                const int ng = g4 * 4 + j;
                MMA_F16(sacc[2 * ng], qh4, bb[j][0], bb[j][2]);
                MMA_F16(sacc[2 * ng + 1], qh4, bb[j][1], bb[j][3]);
            }
        }
    }

    // --- softmax on fragments ---
    float m0 = -1e30f, m1 = -1e30f;
#pragma unroll
    for (int j = 0; j < 32; j++) {
        m0 = fmaxf(m0, fmaxf(sacc[j][0], sacc[j][1]));
        m1 = fmaxf(m1, fmaxf(sacc[j][2], sacc[j][3]));
    }
    m0 = fmaxf(m0, __shfl_xor_sync(0xffffffffu, m0, 1));
    m0 = fmaxf(m0, __shfl_xor_sync(0xffffffffu, m0, 2));
    m1 = fmaxf(m1, __shfl_xor_sync(0xffffffffu, m1, 1));
    m1 = fmaxf(m1, __shfl_xor_sync(0xffffffffu, m1, 2));

    float sum0 = 0.f, sum1 = 0.f;
#pragma unroll
    for (int j = 0; j < 32; j++) {
        float e0 = __expf((sacc[j][0] - m0) * 0.125f);
        float e1 = __expf((sacc[j][1] - m0) * 0.125f);
        float e2 = __expf((sacc[j][2] - m1) * 0.125f);
        float e3 = __expf((sacc[j][3] - m1) * 0.125f);
        sacc[j][0] = e0; sacc[j][1] = e1; sacc[j][2] = e2; sacc[j][3] = e3;
        sum0 += e0 + e1; sum1 += e2 + e3;
    }
    sum0 += __shfl_xor_sync(0xffffffffu, sum0, 1);
    sum0 += __shfl_xor_sync(0xffffffffu, sum0, 2);
    sum1 += __shfl_xor_sync(0xffffffffu, sum1, 1);
    sum1 += __shfl_xor_sync(0xffffffffu, sum1, 2);
    const float inv0 = __frcp_rn(sum0), inv1 = __frcp_rn(sum1);

    // --- ctx = P * Vp (1-term, P plain fp16) ---
    float cacc[8][4];
#pragma unroll
    for (int nt = 0; nt < 8; nt++)
#pragma unroll
        for (int q = 0; q < 4; q++) cacc[nt][q] = 0.f;

#pragma unroll
    for (int s = 0; s < 16; s++) {
        uint32_t ap[4], bb[4][4];
        ap[0] = pack_h2(sacc[2 * s][0],     sacc[2 * s][1]);
        ap[1] = pack_h2(sacc[2 * s][2],     sacc[2 * s][3]);
        ap[2] = pack_h2(sacc[2 * s + 1][0], sacc[2 * s + 1][1]);
        ap[3] = pack_h2(sacc[2 * s + 1][2], sacc[2 * s + 1][3]);
#pragma unroll
        for (int ng = 0; ng < 4; ng++)
            LDMATRIX_X4_T(bb[ng][0], bb[ng][1], bb[ng][2], bb[ng][3],
                          sbase + AV + s * (16 * 144) + lofs + ng * 32);
#pragma unroll
        for (int ng = 0; ng < 4; ng++) {
            MMA_F16(cacc[2 * ng], ap, bb[ng][0], bb[ng][1]);
            MMA_F16(cacc[2 * ng + 1], ap, bb[ng][2], bb[ng][3]);
        }
    }

    // --- epilogue: normalize, write plain fp16 ctx ---
    const int g = lane >> 2, tig = lane & 3;
    const size_t r0 = (size_t)(b * TT + t0 + wm + g) * DD + h * 64;
    const size_t r1 = r0 + 8 * DD;
#pragma unroll
    for (int nt = 0; nt < 8; nt++) {
        const int col = nt * 8 + 2 * tig;
        *(uint32_t*)(Ch + r0 + col) = pack_h2(cacc[nt][0] * inv0, cacc[nt][1] * inv0);
        *(uint32_t*)(Ch + r1 + col) = pack_h2(cacc[nt][2] * inv1, cacc[nt][3] * inv1);
    }
}

// ---------------------------------------------------------------------------
// Launch
// ---------------------------------------------------------------------------
extern "C" void kernel_launch(void* const* d_in, const int* in_sizes, int n_in,
                              void* d_out, int out_size)
{
    const float* x  = (const float*)d_in[0];
    const float* Wq = (const float*)d_in[1];
    const float* Wk = (const float*)d_in[2];
    const float* Wv = (const float*)d_in[3];
    const float* Ek = (const float*)d_in[4];
    const float* Ev = (const float*)d_in[5];
    const float* Wo = (const float*)d_in[6];
    const float* bo = (const float*)d_in[7];
    float* out = (float*)d_out;

    half_t *Ap, *Qhp, *Qlp, *Khp, *Klp, *Vbp, *Wtp;
    half_t *Ethp, *Etlp, *Kphp, *Kplp, *Vpp;
    cudaGetSymbolAddress((void**)&Ap,  g_A);
    cudaGetSymbolAddress((void**)&Qhp, g_Qh);
    cudaGetSymbolAddress((void**)&Qlp, g_Ql);
    cudaGetSymbolAddress((void**)&Khp, g_Kh);
    cudaGetSymbolAddress((void**)&Klp, g_Kl);
    cudaGetSymbolAddress((void**)&Vbp, g_V);
    cudaGetSymbolAddress((void**)&Wtp, g_Wt);
    cudaGetSymbolAddress((void**)&Ethp, g_Eth);
    cudaGetSymbolAddress((void**)&Etlp, g_Etl);
    cudaGetSymbolAddress((void**)&Kphp, g_Kph);
    cudaGetSymbolAddress((void**)&Kplp, g_Kpl);
    cudaGetSymbolAddress((void**)&Vpp, g_Vp);

    const size_t WSZ = (size_t)DD * DD;

    cudaFuncSetAttribute(tc_gemm<1>, cudaFuncAttributeMaxDynamicSharedMemorySize, TC_SMEM);
    cudaFuncSetAttribute(tc_gemm<0>, cudaFuncAttributeMaxDynamicSharedMemorySize, TC_SMEM);
    cudaFuncSetAttribute(proj_mma, cudaFuncAttributeMaxDynamicSharedMemorySize, PROJ_SMEM);
    cudaFuncSetAttribute(attn_mma, cudaFuncAttributeMaxDynamicSharedMemorySize, ATTN_SMEM);

    // 1) convert x -> fp16 plain
    conv_kernel<<<2048, 256>>>(x, Ap, MROWS * DD / 4);
    // 2) transpose+convert weights (plain) + split E
    wconv_kernel<<<dim3(DD / 32, DD / 32, 4), 256>>>(Wq, Wk, Wv, Wo, Wtp);
    esplit_kernel<<<dim3(KP / 32, TT / 32, 2), 256>>>(Ek, Ev, Ethp, Etlp);

    // 3) fused QKV projection (1-term): B = concat(WqT, WkT, WvT)
    //    Q, K routed split; V plain.
    tc_gemm<1><<<dim3(3 * DD / 128, MROWS / 128), 256, TC_SMEM>>>(
        Ap, Wtp, nullptr, nullptr, Qhp, Qlp, Khp, Klp, Vbp, DD);

    // 4) low-rank projections (z=0: Kp 3-term split out; z=1: Vp 2-term plain)
    proj_mma<<<dim3(KP / 128, BHN, 2), 256, PROJ_SMEM>>>(
        Ethp, Etlp, Khp, Klp, Vbp, Kphp, Kplp, Vpp);

    // 5) fused attention -> ctx plain fp16 into A buffer
    attn_mma<<<dim3(TT / 128, BHN), 256, ATTN_SMEM>>>(
        Qhp, Qlp, Kphp, Kplp, Vpp, Ap);

    // 6) output projection + bias (1-term, fp32 out)
    tc_gemm<0><<<dim3(DD / 128, MROWS / 128), 256, TC_SMEM>>>(
        Ap, Wtp + 3 * WSZ, out, bo, nullptr, nullptr, nullptr, nullptr, nullptr, DD);
}

// round 12
// speedup vs baseline: 2.0833x; 1.0422x over previous
#include <cuda_runtime.h>
#include <cuda_fp16.h>
#include <cstdint>
#include <math.h>

// Problem constants
#define BB 4
#define TT 4096
#define DD 1024
#define HH 16
#define KP 256
#define DK 64
#define MROWS (BB*TT)          // 16384
#define BHN (BB*HH)            // 64

typedef __half half_t;

// ---------------------------------------------------------------------------
// Scratch (static device globals; no allocation allowed)
// ---------------------------------------------------------------------------
__device__ half_t g_A [(size_t)MROWS * DD];      // x plain fp16 (later ctx plain)
__device__ half_t g_Qh[(size_t)MROWS * DD];      // Q split (exponent path)
__device__ half_t g_Ql[(size_t)MROWS * DD];
__device__ half_t g_K [(size_t)MROWS * DD];      // plain
__device__ half_t g_V [(size_t)MROWS * DD];      // plain
__device__ half_t g_Wt[4][(size_t)DD * DD];      // transposed [N][K], plain
__device__ half_t g_Eth[(size_t)2 * KP * TT];    // E^T split hi [z][kp][t]
__device__ half_t g_Etl[(size_t)2 * KP * TT];    // E^T split lo
__device__ half_t g_Kp[(size_t)BHN * KP * DK];   // plain
__device__ half_t g_Vp[(size_t)BHN * KP * DK];   // plain

// ---------------------------------------------------------------------------
// Helpers
// ---------------------------------------------------------------------------
__device__ __forceinline__ uint32_t smem_u32(const void* p) {
    uint32_t a;
    asm("{ .reg .u64 t; cvta.to.shared.u64 t, %1; cvt.u32.u64 %0, t; }" : "=r"(a) : "l"(p));
    return a;
}

#define CP_ASYNC16(dst, src) \
    asm volatile("cp.async.cg.shared.global [%0], [%1], 16;" :: "r"(dst), "l"(src))
#define CP_COMMIT() asm volatile("cp.async.commit_group;")
#define CP_WAIT1()  asm volatile("cp.async.wait_group 1;" ::: "memory")
#define CP_WAIT0()  asm volatile("cp.async.wait_group 0;" ::: "memory")

#define LDMATRIX_X4(r0, r1, r2, r3, addr) \
    asm volatile("ldmatrix.sync.aligned.m8n8.x4.shared.b16 {%0,%1,%2,%3}, [%4];" \
        : "=r"(r0), "=r"(r1), "=r"(r2), "=r"(r3) : "r"(addr))
#define LDMATRIX_X4_T(r0, r1, r2, r3, addr) \
    asm volatile("ldmatrix.sync.aligned.m8n8.x4.trans.shared.b16 {%0,%1,%2,%3}, [%4];" \
        : "=r"(r0), "=r"(r1), "=r"(r2), "=r"(r3) : "r"(addr))

#define MMA_F16(d, a, b0_, b1_) \
    asm volatile("mma.sync.aligned.m16n8k16.row.col.f32.f16.f16.f32 " \
        "{%0,%1,%2,%3},{%4,%5,%6,%7},{%8,%9},{%0,%1,%2,%3};" \
        : "+f"((d)[0]), "+f"((d)[1]), "+f"((d)[2]), "+f"((d)[3]) \
        : "r"((a)[0]), "r"((a)[1]), "r"((a)[2]), "r"((a)[3]), "r"(b0_), "r"(b1_))

__device__ __forceinline__ uint32_t pack_h2(float a, float b) {
    __half2 t = __floats2half2_rn(a, b);
    return *(uint32_t*)&t;
}
__device__ __forceinline__ void split2h(float a, float b, uint32_t& hi, uint32_t& lo) {
    __half2 h = __floats2half2_rn(a, b);
    hi = *(uint32_t*)&h;
    lo = pack_h2(a - __low2float(h), b - __high2float(h));
}

// ---------------------------------------------------------------------------
// Convert fp32 -> fp16 plain (vectorized x4)
// ---------------------------------------------------------------------------
__global__ __launch_bounds__(256) void conv_kernel(
    const float* __restrict__ src, half_t* __restrict__ dst, int n4)
{
    uint32_t* d2 = (uint32_t*)dst;
    int stride = gridDim.x * blockDim.x;
    for (int i = blockIdx.x * blockDim.x + threadIdx.x; i < n4; i += stride) {
        float4 v = ((const float4*)src)[i];
        d2[2 * i + 0] = pack_h2(v.x, v.y);
        d2[2 * i + 1] = pack_h2(v.z, v.w);
    }
}

// Transpose + convert all 4 weights (grid.z selects): [D][D] fp32 -> [N][K] fp16
__global__ __launch_bounds__(256) void wconv_kernel(
    const float* __restrict__ W0, const float* __restrict__ W1,
    const float* __restrict__ W2, const float* __restrict__ W3,
    half_t* __restrict__ WtAll)
{
    __shared__ float t[32][33];
    const int z = blockIdx.z;
    const float* W = (z == 0) ? W0 : (z == 1) ? W1 : (z == 2) ? W2 : W3;
    half_t* Wt = WtAll + (size_t)z * DD * DD;
    const int c0 = blockIdx.x * 32, r0 = blockIdx.y * 32;
    const int tx = threadIdx.x & 31, ty = threadIdx.x >> 5;
#pragma unroll
    for (int r = 0; r < 32; r += 8)
        t[ty + r][tx] = W[(size_t)(r0 + ty + r) * DD + c0 + tx];
    __syncthreads();
#pragma unroll
    for (int r = 0; r < 32; r += 8)
        Wt[(size_t)(c0 + ty + r) * DD + r0 + tx] = __float2half(t[tx][ty + r]);
}

// Transpose + split E (grid.z selects Ek/Ev): [T][KP] fp32 -> [KP][T] fp16 hi/lo
__global__ __launch_bounds__(256) void esplit_kernel(
    const float* __restrict__ E0, const float* __restrict__ E1,
    half_t* __restrict__ hiT, half_t* __restrict__ loT)
{
    __shared__ float t[32][33];
    const int z = blockIdx.z;
    const float* E = z ? E1 : E0;
    half_t* hi = hiT + (size_t)z * KP * TT;
    half_t* lo = loT + (size_t)z * KP * TT;
    const int c0 = blockIdx.x * 32, r0 = blockIdx.y * 32;
    const int tx = threadIdx.x & 31, ty = threadIdx.x >> 5;
#pragma unroll
    for (int r = 0; r < 32; r += 8)
        t[ty + r][tx] = E[(size_t)(r0 + ty + r) * KP + c0 + tx];
    __syncthreads();
#pragma unroll
    for (int r = 0; r < 32; r += 8) {
        float v = t[tx][ty + r];
        half_t h = __float2half(v);
        size_t o = (size_t)(c0 + ty + r) * TT + r0 + tx;
        hi[o] = h;
        lo[o] = __float2half(v - __half2float(h));
    }
}

// ---------------------------------------------------------------------------
// mma.sync fp16 GEMM: C = A[M,K] * B^T   (1-term A)
// MODE 0: fp32 out (+bias).
// MODE 1: QKV routing — col block 0 -> Q split, 1 -> K plain, 2 -> V plain.
// Block 128x128, K-chunk 32, 8 warps, 3-stage cp.async pipeline, 2 CTAs/SM.
// ---------------------------------------------------------------------------
#define GTILE   10240                  // 128 rows * 80 B
#define GSTAGE  (2 * GTILE)            // A, B
#define TC_SMEM (3 * GSTAGE)           // 61440

template<int MODE>
__global__ __launch_bounds__(256, 2) void tc_gemm(
    const half_t* __restrict__ Ah, const half_t* __restrict__ Bh,
    float* __restrict__ C, const float* __restrict__ bias,
    half_t* __restrict__ Qh, half_t* __restrict__ Ql,
    half_t* __restrict__ Ko, half_t* __restrict__ Vo, int Kn)
{
    extern __shared__ char smem[];
    const uint32_t sbase = smem_u32(smem);
    const int tid = threadIdx.x, wid = tid >> 5, lane = tid & 31;
    const int warp_m = wid >> 1, warp_n = wid & 1;
    const int m0 = blockIdx.y * 128;
    const int n0g = blockIdx.x * 128;

    float acc[2][8][4];
#pragma unroll
    for (int mt = 0; mt < 2; mt++)
#pragma unroll
        for (int nt = 0; nt < 8; nt++)
#pragma unroll
            for (int q = 0; q < 4; q++) acc[mt][nt][q] = 0.f;

    const uint32_t lofs = ((((lane >> 3) & 1) * 8 + (lane & 7)) * 80u) + ((lane >> 4) * 16u);
    const int ld_row0 = tid >> 2;
    const int ld_col  = tid & 3;

    const int NC = Kn >> 5;
#define LOAD_STAGE(s, k0v) do {                                                   \
        const uint32_t stg = sbase + (uint32_t)(s) * GSTAGE;                      \
        _Pragma("unroll")                                                         \
        for (int i = 0; i < 4; i++) {                                             \
            const int t = i >> 1;                                                 \
            const int row = (i & 1) * 64 + ld_row0;                               \
            const half_t* sp = (t == 0 ? Ah : Bh);                                \
            const int grow = (t == 0 ? m0 : n0g) + row;                           \
            CP_ASYNC16(stg + t * GTILE + row * 80 + ld_col * 16,                  \
                       sp + (size_t)grow * Kn + (k0v) + ld_col * 8);              \
        }                                                                         \
        CP_COMMIT();                                                              \
    } while (0)

    LOAD_STAGE(0, 0);
    LOAD_STAGE(1, 32);

    for (int c = 0; c < NC; c++) {
        const bool more = (c + 2 < NC);
        if (more) { CP_WAIT1(); } else { CP_WAIT0(); }   // tail: full drain
        __syncthreads();
        if (more) LOAD_STAGE((c + 2) % 3, (c + 2) << 5);

        const uint32_t stg = sbase + (uint32_t)(c % 3) * GSTAGE;
        const uint32_t a_base = stg + (warp_m * 32) * 80 + lofs;
        const uint32_t b_base = stg + GTILE + (warp_n * 64) * 80 + lofs;

#pragma unroll
        for (int ks = 0; ks < 2; ks++) {
            uint32_t ah[2][4], b[4][4];
#pragma unroll
            for (int mt = 0; mt < 2; mt++)
                LDMATRIX_X4(ah[mt][0], ah[mt][1], ah[mt][2], ah[mt][3],
                            a_base + mt * (16 * 80) + ks * 32);
#pragma unroll
            for (int nq = 0; nq < 4; nq++)
                LDMATRIX_X4(b[nq][0], b[nq][1], b[nq][2], b[nq][3],
                            b_base + nq * (16 * 80) + ks * 32);
#pragma unroll
            for (int mt = 0; mt < 2; mt++)
#pragma unroll
                for (int nt = 0; nt < 8; nt++) {
                    const int nq = nt >> 1, sel = nt & 1;
                    MMA_F16(acc[mt][nt], ah[mt], b[nq][sel], b[nq][sel + 2]);
                }
        }
    }
#undef LOAD_STAGE

    const int g = lane >> 2, tig = lane & 3;
#pragma unroll
    for (int mt = 0; mt < 2; mt++) {
        const int row0 = m0 + warp_m * 32 + mt * 16 + g;
#pragma unroll
        for (int nt = 0; nt < 8; nt++) {
            const int colg = n0g + warp_n * 64 + nt * 8 + 2 * tig;
            if (MODE == 0) {
                float bx = 0.f, by = 0.f;
                if (bias) { bx = bias[colg]; by = bias[colg + 1]; }
                *(float2*)(C + (size_t)row0 * DD + colg) =
                    make_float2(acc[mt][nt][0] + bx, acc[mt][nt][1] + by);
                *(float2*)(C + (size_t)(row0 + 8) * DD + colg) =
                    make_float2(acc[mt][nt][2] + bx, acc[mt][nt][3] + by);
            } else {
                const int which = colg >> 10;
                const int col = colg & 1023;
                const size_t o0 = (size_t)row0 * DD + col;
                const size_t o1 = (size_t)(row0 + 8) * DD + col;
                if (which == 0) {
                    uint32_t hi, lo;
                    split2h(acc[mt][nt][0], acc[mt][nt][1], hi, lo);
                    *(uint32_t*)(Qh + o0) = hi; *(uint32_t*)(Ql + o0) = lo;
                    split2h(acc[mt][nt][2], acc[mt][nt][3], hi, lo);
                    *(uint32_t*)(Qh + o1) = hi; *(uint32_t*)(Ql + o1) = lo;
                } else {
                    half_t* O = (which == 1) ? Ko : Vo;
                    *(uint32_t*)(O + o0) = pack_h2(acc[mt][nt][0], acc[mt][nt][1]);
                    *(uint32_t*)(O + o1) = pack_h2(acc[mt][nt][2], acc[mt][nt][3]);
                }
            }
        }
    }
}

// ---------------------------------------------------------------------------
// Low-rank projection on MMA, 3-stage pipeline (uniform 2-term now):
//   Cp[kp][d] = (Eh+El)^T[kp][t] * X[t][h*64+d], plain output
//   z=0: X=K -> Kp;  z=1: X=V -> Vp
// grid = (KP/128, BHN, 2)
// ---------------------------------------------------------------------------
#define PAH 0
#define PALo 10240
#define PB  20480
#define PSTAGE (PB + 32 * 144)          // 25088
#define PROJ_SMEM (3 * PSTAGE)          // 75264

__global__ __launch_bounds__(256) void proj_mma(
    const half_t* __restrict__ Eh, const half_t* __restrict__ El,
    const half_t* __restrict__ Kb, const half_t* __restrict__ Vb,
    half_t* __restrict__ Kp, half_t* __restrict__ Vp)
{
    extern __shared__ char smem[];
    const uint32_t sbase = smem_u32(smem);
    const int tid = threadIdx.x, wid = tid >> 5, lane = tid & 31;
    const int m0k = blockIdx.x * 128;
    const int bh = blockIdx.y, z = blockIdx.z;
    const int b = bh >> 4, h = bh & 15;

    const half_t* X = z ? Vb : Kb;
    half_t* O = z ? Vp : Kp;
    const size_t eoff = (size_t)z * KP * TT;
    const size_t brow = (size_t)b * TT;
    const int hcol = h * 64;

    float cacc[8][4];
#pragma unroll
    for (int nt = 0; nt < 8; nt++)
#pragma unroll
        for (int q = 0; q < 4; q++) cacc[nt][q] = 0.f;

    const uint32_t lofsA = (lane & 15) * 80u + ((lane >> 4) * 16u);
    const uint32_t lofsB = (lane & 15) * 144u + ((lane >> 4) * 16u);
    const int wm = wid * 16;

#define PROJ_LOAD(s, k0v) do {                                                    \
        const uint32_t stg = sbase + (uint32_t)(s) * PSTAGE;                      \
        _Pragma("unroll")                                                         \
        for (int i = 0; i < 2; i++) {                                             \
            const int idx = tid + i * 256;                                        \
            const int r = idx >> 2, cc = idx & 3;                                 \
            const size_t gof = (size_t)(m0k + r) * TT + (k0v) + cc * 8;           \
            CP_ASYNC16(stg + PAH + r * 80 + cc * 16, Eh + eoff + gof);            \
            CP_ASYNC16(stg + PALo + r * 80 + cc * 16, El + eoff + gof);           \
        }                                                                         \
        {                                                                         \
            const int r = tid >> 3, cc = tid & 7;                                 \
            const size_t gof = (brow + (k0v) + r) * DD + hcol + cc * 8;           \
            CP_ASYNC16(stg + PB + r * 144 + cc * 16, X + gof);                    \
        }                                                                         \
        CP_COMMIT();                                                              \
    } while (0)

    PROJ_LOAD(0, 0);
    PROJ_LOAD(1, 32);
    const int NC = TT >> 5;
    for (int c = 0; c < NC; c++) {
        const bool more = (c + 2 < NC);
        if (more) { CP_WAIT1(); } else { CP_WAIT0(); }   // tail: full drain
        __syncthreads();
        if (more) PROJ_LOAD((c + 2) % 3, (c + 2) << 5);

        const uint32_t stg = sbase + (uint32_t)(c % 3) * PSTAGE;
#pragma unroll
        for (int s = 0; s < 2; s++) {
            uint32_t ah[4], al[4], bb[4][4];
            LDMATRIX_X4(ah[0], ah[1], ah[2], ah[3], stg + PAH + wm * 80 + lofsA + s * 32);
            LDMATRIX_X4(al[0], al[1], al[2], al[3], stg + PALo + wm * 80 + lofsA + s * 32);
#pragma unroll
            for (int ng = 0; ng < 4; ng++)
                LDMATRIX_X4_T(bb[ng][0], bb[ng][1], bb[ng][2], bb[ng][3],
                              stg + PB + s * (16 * 144) + lofsB + ng * 32);
#pragma unroll
            for (int ng = 0; ng < 4; ng++) {
                MMA_F16(cacc[2 * ng], ah, bb[ng][0], bb[ng][1]);
                MMA_F16(cacc[2 * ng + 1], ah, bb[ng][2], bb[ng][3]);
            }
#pragma unroll
            for (int ng = 0; ng < 4; ng++) {
                MMA_F16(cacc[2 * ng], al, bb[ng][0], bb[ng][1]);
                MMA_F16(cacc[2 * ng + 1], al, bb[ng][2], bb[ng][3]);
            }
        }
    }
#undef PROJ_LOAD

    const int g = lane >> 2, tig = lane & 3;
    const size_t obase = (size_t)bh * KP * DK;
#pragma unroll
    for (int nt = 0; nt < 8; nt++) {
        const int row0 = m0k + wm + g;
        const int col = nt * 8 + 2 * tig;
        *(uint32_t*)(O + obase + (size_t)row0 * DK + col) =
            pack_h2(cacc[nt][0], cacc[nt][1]);
        *(uint32_t*)(O + obase + (size_t)(row0 + 8) * DK + col) =
            pack_h2(cacc[nt][2], cacc[nt][3]);
    }
}

// ---------------------------------------------------------------------------
// Fused MMA attention per (bh, 128-row t-tile):
//   S = (Qh+Ql)*Kp^T  (2 MMAs/tile — Q split, Kp plain)
//   softmax on fragments; ctx = P*Vp (1-term, P plain); ctx plain to Ch.
// ---------------------------------------------------------------------------
#define AQH 0
#define AQL (AQH + 128 * 144)
#define AK  (AQL + 128 * 144)
#define AV  (AK  + 256 * 144)
#define ATTN_SMEM (AV + 256 * 144)      // 110592

__global__ __launch_bounds__(256) void attn_mma(
    const half_t* __restrict__ Qh, const half_t* __restrict__ Ql,
    const half_t* __restrict__ Kp, const half_t* __restrict__ Vp,
    half_t* __restrict__ Ch)
{
    extern __shared__ char smem[];
    const uint32_t sbase = smem_u32(smem);
    const int tid = threadIdx.x, wid = tid >> 5, lane = tid & 31;
    const int bh = blockIdx.y, b = bh >> 4, h = bh & 15;
    const int t0 = blockIdx.x * 128;

    const size_t qbase = (size_t)(b * TT + t0) * DD + h * 64;
    for (int idx = tid; idx < 128 * 8; idx += 256) {
        const int r = idx >> 3, c = idx & 7;
        const size_t go = qbase + (size_t)r * DD + c * 8;
        *(uint4*)(smem + AQH + r * 144 + c * 16) = *(const uint4*)(Qh + go);
        *(uint4*)(smem + AQL + r * 144 + c * 16) = *(const uint4*)(Ql + go);
    }
    const size_t kpb = (size_t)bh * KP * DK;
    for (int idx = tid; idx < 256 * 8; idx += 256) {
        const int r = idx >> 3, c = idx & 7;
        const size_t go = kpb + (size_t)r * DK + c * 8;
        *(uint4*)(smem + AK + r * 144 + c * 16) = *(const uint4*)(Kp + go);
        *(uint4*)(smem + AV + r * 144 + c * 16) = *(const uint4*)(Vp + go);
    }
    __syncthreads();

    const int wm = wid * 16;
    const uint32_t lofs = (lane & 15) * 144u + ((lane >> 4) * 16u);

    // --- scores (2-term: qh*kp + ql*kp), ng in batches of 4 ---
    float sacc[32][4];
#pragma unroll
    for (int j = 0; j < 32; j++)
#pragma unroll
        for (int q = 0; q < 4; q++) sacc[j][q] = 0.f;

#pragma unroll
    for (int s = 0; s < 4; s++) {
        uint32_t qh4[4], ql4[4], bb[4][4];
        LDMATRIX_X4(qh4[0], qh4[1], qh4[2], qh4[3], sbase + AQH + wm * 144 + lofs + s * 32);
        LDMATRIX_X4(ql4[0], ql4[1], ql4[2], ql4[3], sbase + AQL + wm * 144 + lofs + s * 32);
#pragma unroll
        for (int g4 = 0; g4 < 4; g4++) {
#pragma unroll
            for (int j = 0; j < 4; j++)
                LDMATRIX_X4(bb[j][0], bb[j][1], bb[j][2], bb[j][3],
                            sbase + AK + (g4 * 4 + j) * (16 * 144) + lofs + s * 32);
#pragma unroll
            for (int j = 0; j < 4; j++) {
                const int ng = g4 * 4 + j;
                MMA_F16(sacc[2 * ng], qh4, bb[j][0], bb[j][2]);
                MMA_F16(sacc[2 * ng + 1], qh4, bb[j][1], bb[j][3]);
            }
#pragma unroll
            for (int j = 0; j < 4; j++) {
                const int ng = g4 * 4 + j;
                MMA_F16(sacc[2 * ng], ql4, bb[j][0], bb[j][2]);
                MMA_F16(sacc[2 * ng + 1], ql4, bb[j][1], bb[j][3]);
            }
        }
    }

    // --- softmax on fragments ---
    float m0 = -1e30f, m1 = -1e30f;
#pragma unroll
    for (int j = 0; j < 32; j++) {
        m0 = fmaxf(m0, fmaxf(sacc[j][0], sacc[j][1]));
        m1 = fmaxf(m1, fmaxf(sacc[j][2], sacc[j][3]));
    }
    m0 = fmaxf(m0, __shfl_xor_sync(0xffffffffu, m0, 1));
    m0 = fmaxf(m0, __shfl_xor_sync(0xffffffffu, m0, 2));
    m1 = fmaxf(m1, __shfl_xor_sync(0xffffffffu, m1, 1));
    m1 = fmaxf(m1, __shfl_xor_sync(0xffffffffu, m1, 2));

    float sum0 = 0.f, sum1 = 0.f;
#pragma unroll
    for (int j = 0; j < 32; j++) {
        float e0 = __expf((sacc[j][0] - m0) * 0.125f);
        float e1 = __expf((sacc[j][1] - m0) * 0.125f);
        float e2 = __expf((sacc[j][2] - m1) * 0.125f);
        float e3 = __expf((sacc[j][3] - m1) * 0.125f);
        sacc[j][0] = e0; sacc[j][1] = e1; sacc[j][2] = e2; sacc[j][3] = e3;
        sum0 += e0 + e1; sum1 += e2 + e3;
    }
    sum0 += __shfl_xor_sync(0xffffffffu, sum0, 1);
    sum0 += __shfl_xor_sync(0xffffffffu, sum0, 2);
    sum1 += __shfl_xor_sync(0xffffffffu, sum1, 1);
    sum1 += __shfl_xor_sync(0xffffffffu, sum1, 2);
    const float inv0 = __frcp_rn(sum0), inv1 = __frcp_rn(sum1);

    // --- ctx = P * Vp (1-term, P plain fp16) ---
    float cacc[8][4];
#pragma unroll
    for (int nt = 0; nt < 8; nt++)
#pragma unroll
        for (int q = 0; q < 4; q++) cacc[nt][q] = 0.f;

#pragma unroll
    for (int s = 0; s < 16; s++) {
        uint32_t ap[4], bb[4][4];
        ap[0] = pack_h2(sacc[2 * s][0],     sacc[2 * s][1]);
        ap[1] = pack_h2(sacc[2 * s][2],     sacc[2 * s][3]);
        ap[2] = pack_h2(sacc[2 * s + 1][0], sacc[2 * s + 1][1]);
        ap[3] = pack_h2(sacc[2 * s + 1][2], sacc[2 * s + 1][3]);
#pragma unroll
        for (int ng = 0; ng < 4; ng++)
            LDMATRIX_X4_T(bb[ng][0], bb[ng][1], bb[ng][2], bb[ng][3],
                          sbase + AV + s * (16 * 144) + lofs + ng * 32);
#pragma unroll
        for (int ng = 0; ng < 4; ng++) {
            MMA_F16(cacc[2 * ng], ap, bb[ng][0], bb[ng][1]);
            MMA_F16(cacc[2 * ng + 1], ap, bb[ng][2], bb[ng][3]);
        }
    }

    // --- epilogue: normalize, write plain fp16 ctx ---
    const int g = lane >> 2, tig = lane & 3;
    const size_t r0 = (size_t)(b * TT + t0 + wm + g) * DD + h * 64;
    const size_t r1 = r0 + 8 * DD;
#pragma unroll
    for (int nt = 0; nt < 8; nt++) {
        const int col = nt * 8 + 2 * tig;
        *(uint32_t*)(Ch + r0 + col) = pack_h2(cacc[nt][0] * inv0, cacc[nt][1] * inv0);
        *(uint32_t*)(Ch + r1 + col) = pack_h2(cacc[nt][2] * inv1, cacc[nt][3] * inv1);
    }
}

// ---------------------------------------------------------------------------
// Launch
// ---------------------------------------------------------------------------
extern "C" void kernel_launch(void* const* d_in, const int* in_sizes, int n_in,
                              void* d_out, int out_size)
{
    const float* x  = (const float*)d_in[0];
    const float* Wq = (const float*)d_in[1];
    const float* Wk = (const float*)d_in[2];
    const float* Wv = (const float*)d_in[3];
    const float* Ek = (const float*)d_in[4];
    const float* Ev = (const float*)d_in[5];
    const float* Wo = (const float*)d_in[6];
    const float* bo = (const float*)d_in[7];
    float* out = (float*)d_out;

    half_t *Ap, *Qhp, *Qlp, *Kbp, *Vbp, *Wtp;
    half_t *Ethp, *Etlp, *Kpp, *Vpp;
    cudaGetSymbolAddress((void**)&Ap,  g_A);
    cudaGetSymbolAddress((void**)&Qhp, g_Qh);
    cudaGetSymbolAddress((void**)&Qlp, g_Ql);
    cudaGetSymbolAddress((void**)&Kbp, g_K);
    cudaGetSymbolAddress((void**)&Vbp, g_V);
    cudaGetSymbolAddress((void**)&Wtp, g_Wt);
    cudaGetSymbolAddress((void**)&Ethp, g_Eth);
    cudaGetSymbolAddress((void**)&Etlp, g_Etl);
    cudaGetSymbolAddress((void**)&Kpp, g_Kp);
    cudaGetSymbolAddress((void**)&Vpp, g_Vp);

    const size_t WSZ = (size_t)DD * DD;

    cudaFuncSetAttribute(tc_gemm<1>, cudaFuncAttributeMaxDynamicSharedMemorySize, TC_SMEM);
    cudaFuncSetAttribute(tc_gemm<0>, cudaFuncAttributeMaxDynamicSharedMemorySize, TC_SMEM);
    cudaFuncSetAttribute(proj_mma, cudaFuncAttributeMaxDynamicSharedMemorySize, PROJ_SMEM);
    cudaFuncSetAttribute(attn_mma, cudaFuncAttributeMaxDynamicSharedMemorySize, ATTN_SMEM);

    // 1) convert x -> fp16 plain
    conv_kernel<<<2048, 256>>>(x, Ap, MROWS * DD / 4);
    // 2) transpose+convert weights (plain) + split E
    wconv_kernel<<<dim3(DD / 32, DD / 32, 4), 256>>>(Wq, Wk, Wv, Wo, Wtp);
    esplit_kernel<<<dim3(KP / 32, TT / 32, 2), 256>>>(Ek, Ev, Ethp, Etlp);

    // 3) fused QKV projection (1-term): B = concat(WqT, WkT, WvT)
    //    Q split out; K, V plain.
    tc_gemm<1><<<dim3(3 * DD / 128, MROWS / 128), 256, TC_SMEM>>>(
        Ap, Wtp, nullptr, nullptr, Qhp, Qlp, Kbp, Vbp, DD);

    // 4) low-rank projections (uniform 2-term, plain outputs)
    proj_mma<<<dim3(KP / 128, BHN, 2), 256, PROJ_SMEM>>>(
        Ethp, Etlp, Kbp, Vbp, Kpp, Vpp);

    // 5) fused attention -> ctx plain fp16 into A buffer
    attn_mma<<<dim3(TT / 128, BHN), 256, ATTN_SMEM>>>(
        Qhp, Qlp, Kpp, Vpp, Ap);

    // 6) output projection + bias (1-term, fp32 out)
    tc_gemm<0><<<dim3(DD / 128, MROWS / 128), 256, TC_SMEM>>>(
        Ap, Wtp + 3 * WSZ, out, bo, nullptr, nullptr, nullptr, nullptr, DD);
}